// round 9
// baseline (speedup 1.0000x reference)
#include <cuda_runtime.h>
#include <cuda_bf16.h>
#include <math.h>
#include <stdint.h>

#define Bb 2
#define Tt 1024
#define Cc 2048
#define Hh 32
#define Dd 64
#define NT (Bb*Tt)
#define L3 96

// ---------------- scratch ----------------
__device__ __align__(16) float s_h [NT*L3];
__device__ __align__(16) float s_yq[NT*Cc];
__device__ __align__(16) float s_yk[NT*Cc];
__device__ __align__(16) float s_yv[NT*Cc];
__device__ __align__(16) float s_qh[NT*Cc];
__device__ __align__(16) float s_kh[NT*Cc];
__device__ __align__(16) float s_vh[NT*Cc];
__device__ __align__(16) float s_att[NT*Cc];

// bf16 hi/lo planes (pre-split GEMM operands)
__device__ __align__(16) __nv_bfloat16 a_hi[3][NT*Cc];   // xr, xk, xv
__device__ __align__(16) __nv_bfloat16 a_lo[3][NT*Cc];
__device__ __align__(16) __nv_bfloat16 o_hi[NT*Cc];      // ln(attn out)
__device__ __align__(16) __nv_bfloat16 o_lo[NT*Cc];
__device__ __align__(16) __nv_bfloat16 w_hi[4][Cc*Cc];   // Wq, Wk, Wv, Wo
__device__ __align__(16) __nv_bfloat16 w_lo[4][Cc*Cc];

// ============ helpers ============
__device__ __forceinline__ uint32_t cvta_sm(const void* p) {
    return (uint32_t)__cvta_generic_to_shared(p);
}
__device__ __forceinline__ void ldsm_x4(uint32_t addr, uint32_t* r) {
    asm volatile("ldmatrix.sync.aligned.m8n8.x4.shared.b16 {%0,%1,%2,%3},[%4];"
        : "=r"(r[0]), "=r"(r[1]), "=r"(r[2]), "=r"(r[3]) : "r"(addr));
}
__device__ __forceinline__ void ldsm_x4t(uint32_t addr, uint32_t* r) {
    asm volatile("ldmatrix.sync.aligned.m8n8.x4.trans.shared.b16 {%0,%1,%2,%3},[%4];"
        : "=r"(r[0]), "=r"(r[1]), "=r"(r[2]), "=r"(r[3]) : "r"(addr));
}
__device__ __forceinline__ void mma_bf16(float* d, const uint32_t* a, const uint32_t* b) {
    asm volatile(
        "mma.sync.aligned.m16n8k16.row.col.f32.bf16.bf16.f32 "
        "{%0,%1,%2,%3},{%4,%5,%6,%7},{%8,%9},{%0,%1,%2,%3};"
        : "+f"(d[0]), "+f"(d[1]), "+f"(d[2]), "+f"(d[3])
        : "r"(a[0]), "r"(a[1]), "r"(a[2]), "r"(a[3]), "r"(b[0]), "r"(b[1]));
}
__device__ __forceinline__ uint32_t packbf(float x, float y) {
    __nv_bfloat162 h = __floats2bfloat162_rn(x, y);
    return *(uint32_t*)&h;
}
__device__ __forceinline__ uint32_t pack_hi2(float x, float y, float& rx, float& ry) {
    __nv_bfloat16 hx = __float2bfloat16_rn(x), hy = __float2bfloat16_rn(y);
    rx = x - __bfloat162float(hx);
    ry = y - __bfloat162float(hy);
    return ((uint32_t)*(uint16_t*)&hy << 16) | *(uint16_t*)&hx;
}
__device__ __forceinline__ void cp16(uint32_t dst, const void* src) {
    asm volatile("cp.async.cg.shared.global [%0], [%1], 16;" :: "r"(dst), "l"(src));
}
__device__ __forceinline__ void cp_commit() {
    asm volatile("cp.async.commit_group;" ::: "memory");
}
template<int N> __device__ __forceinline__ void cp_wait() {
    asm volatile("cp.async.wait_group %0;" :: "n"(N) : "memory");
}

// ---------------- weight pre-split ----------------
__global__ __launch_bounds__(256) void k_wcvt(
    const float* __restrict__ Wq, const float* __restrict__ Wk,
    const float* __restrict__ Wv, const float* __restrict__ Wo)
{
    int m = blockIdx.y;
    const float* src = (m == 0) ? Wq : (m == 1) ? Wk : (m == 2) ? Wv : Wo;
    size_t e = ((size_t)blockIdx.x * 256 + threadIdx.x) * 4;
    float4 v = *(const float4*)(src + e);
    float r0,r1,r2,r3;
    uint2 hi, lo;
    hi.x = pack_hi2(v.x, v.y, r0, r1);
    hi.y = pack_hi2(v.z, v.w, r2, r3);
    lo.x = packbf(r0, r1);
    lo.y = packbf(r2, r3);
    *(uint2*)&w_hi[m][e] = hi;
    *(uint2*)&w_lo[m][e] = lo;
}

// ---------------- LoRA stage 1 (prelude fused: computes xx inline) ----------
__global__ __launch_bounds__(96) void k_lora1(
    const float* __restrict__ x, const float* __restrict__ shift,
    const float* __restrict__ maa_x, const float* __restrict__ w1)
{
    __shared__ float xs[16][128];
    int n0 = blockIdx.x * 16;
    int j  = threadIdx.x;
    float acc[16];
#pragma unroll
    for (int r = 0; r < 16; r++) acc[r] = 0.f;
    for (int k0 = 0; k0 < Cc; k0 += 128) {
        __syncthreads();
        for (int i = threadIdx.x; i < 16*128; i += 96) {
            int r = i >> 7, cc = i & 127;
            int row = n0 + r, c = k0 + cc;
            int t = row & (Tt - 1), b = row >> 10;
            float xv = x[(size_t)row*Cc + c];
            float xp = (t == 0) ? shift[b*Cc + c] : x[(size_t)(row-1)*Cc + c];
            xs[r][cc] = fmaf(xp - xv, maa_x[c], xv);
        }
        __syncthreads();
        for (int k = 0; k < 128; k++) {
            float wv = w1[(k0 + k)*L3 + j];
#pragma unroll
            for (int r = 0; r < 16; r++) acc[r] = fmaf(xs[r][k], wv, acc[r]);
        }
    }
#pragma unroll
    for (int r = 0; r < 16; r++) s_h[(n0 + r)*L3 + j] = tanhf(acc[r]);
}

// ---------------- LoRA stage 2 + mixing (dx inline; writes bf16 hi/lo) ------
__global__ __launch_bounds__(256) void k_mix(
    const float* __restrict__ x, const float* __restrict__ shift,
    const float* __restrict__ w2,
    const float* __restrict__ maa_r, const float* __restrict__ maa_k,
    const float* __restrict__ maa_v)
{
    __shared__ float w2s[96][64];
    __shared__ float hs[16][96];
    int c0 = blockIdx.x * 64;
    int n0 = blockIdx.y * 16;
    int tid = threadIdx.x;
    for (int i = tid; i < 96*64; i += 256) {
        int rr = i >> 6, cc = i & 63;
        w2s[rr][cc] = w2[rr*Cc + c0 + cc];
    }
    for (int i = tid; i < 16*96; i += 256) {
        int rr = i / 96, jj = i % 96;
        hs[rr][jj] = s_h[(n0 + rr)*L3 + jj];
    }
    __syncthreads();
    int col = tid & 63, rg = tid >> 6;        // 4 row-groups x 4 rows
    int c = c0 + col;
    float ar = maa_r[c], ak = maa_k[c], av = maa_v[c];
#pragma unroll
    for (int rr = 0; rr < 4; rr++) {
        int r = rg*4 + rr;
        float m0 = 0.f, m1 = 0.f, m2 = 0.f;
#pragma unroll
        for (int i = 0; i < 32; i++) {
            m0 = fmaf(hs[r][i],      w2s[i][col],      m0);
            m1 = fmaf(hs[r][32 + i], w2s[32 + i][col], m1);
            m2 = fmaf(hs[r][64 + i], w2s[64 + i][col], m2);
        }
        int row = n0 + r;
        int t = row & (Tt - 1), b = row >> 10;
        size_t idx = (size_t)row*Cc + c;
        float xf = x[idx];
        float xp = (t == 0) ? shift[b*Cc + c] : x[idx - Cc];
        float dxf = xp - xf;
        float vr = fmaf(dxf, ar + m0, xf);
        float vk = fmaf(dxf, ak + m1, xf);
        float vv = fmaf(dxf, av + m2, xf);
        __nv_bfloat16 hr = __float2bfloat16_rn(vr);
        __nv_bfloat16 hk = __float2bfloat16_rn(vk);
        __nv_bfloat16 hv = __float2bfloat16_rn(vv);
        a_hi[0][idx] = hr; a_lo[0][idx] = __float2bfloat16_rn(vr - __bfloat162float(hr));
        a_hi[1][idx] = hk; a_lo[1][idx] = __float2bfloat16_rn(vk - __bfloat162float(hk));
        a_hi[2][idx] = hv; a_lo[2][idx] = __float2bfloat16_rn(vv - __bfloat162float(hv));
    }
}

// ============ bf16 3-term GEMM, CTA tile 128x64, warp tile 32x32 ============
// k-tile 32, 2 stages x 24KB.
// stage layout (from stage base SS):
//   A: term*8192 + ksub*4096 + row*32 + swz_chunk*16     (2 terms, 2 ksub, 128 rows)
//   B: 16384 + term*4096 + kr*128 + swz_chunk*16         (2 terms, 32 kr, 8 ch)
#define GEMM_SMEM_BYTES 49152

__device__ __forceinline__ void gemm_cp(
    const __nv_bfloat16* __restrict__ Ah, const __nv_bfloat16* __restrict__ Al,
    const __nv_bfloat16* __restrict__ Bh, const __nv_bfloat16* __restrict__ Bl,
    float* __restrict__ Cm)
{
    extern __shared__ __align__(16) unsigned char smema[];
    const uint32_t sm0 = cvta_sm(smema);
    const int tid = threadIdx.x, lane = tid & 31, wid = tid >> 5;
    const int wm = wid >> 1, wn = wid & 1;
    const int m0 = blockIdx.y * 128, n0 = blockIdx.x * 64;

    auto issue = [&](int kt, int s) {
        uint32_t SS = sm0 + s*24576;
#pragma unroll
        for (int t = 0; t < 4; t++) {          // A: 1024 x 16B
            int idx = tid + t*256;
            int term = idx >> 9, ksub = (idx >> 8) & 1;
            int row = (idx >> 1) & 127, ch = idx & 1;
            const __nv_bfloat16* src = (term ? Al : Ah)
                + (size_t)(m0 + row)*Cc + kt*32 + ksub*16 + ch*8;
            uint32_t dst = SS + term*8192 + ksub*4096 + row*32
                         + ((ch ^ ((row >> 2) & 1))*16);
            cp16(dst, src);
        }
#pragma unroll
        for (int t = 0; t < 2; t++) {          // B: 512 x 16B
            int idx = tid + t*256;
            int term = idx >> 8, kr = (idx >> 3) & 31, ch = idx & 7;
            const __nv_bfloat16* src = (term ? Bl : Bh)
                + (size_t)(kt*32 + kr)*Cc + n0 + ch*8;
            uint32_t dst = SS + 16384 + term*4096 + kr*128 + ((ch ^ (kr & 7))*16);
            cp16(dst, src);
        }
        cp_commit();
    };

    float acc[2][4][4];
#pragma unroll
    for (int i = 0; i < 2; i++)
#pragma unroll
        for (int j = 0; j < 4; j++)
#pragma unroll
            for (int e = 0; e < 4; e++) acc[i][j][e] = 0.f;

    const int rlA = lane & 15;
    const int selA = lane >> 4;
    const int krB = ((lane >> 3) & 1)*8 + (lane & 7);
    const int ncB = lane >> 4;

    issue(0, 0);
    const int NKT = Cc / 32;
    for (int kt = 0; kt < NKT; kt++) {
        int s = kt & 1;
        if (kt + 1 < NKT) { issue(kt + 1, s ^ 1); cp_wait<1>(); }
        else              { cp_wait<0>(); }
        __syncthreads();
        uint32_t SS = sm0 + s*24576;
#pragma unroll
        for (int ksub = 0; ksub < 2; ksub++) {
            uint32_t Ahf[2][4], Alf[2][4], Bhf[4][2], Blf[4][2];
#pragma unroll
            for (int i = 0; i < 2; i++) {
                int row = wm*32 + i*16 + rlA;
                uint32_t off = SS + ksub*4096 + row*32
                             + ((selA ^ ((row >> 2) & 1))*16);
                ldsm_x4(off, Ahf[i]);
                ldsm_x4(off + 8192, Alf[i]);
            }
#pragma unroll
            for (int jj = 0; jj < 2; jj++) {
                int kr = ksub*16 + krB;
                int nchunk = wn*4 + jj*2 + ncB;
                uint32_t off = SS + 16384 + kr*128 + ((nchunk ^ (kr & 7))*16);
                uint32_t tmp[4];
                ldsm_x4t(off, tmp);
                Bhf[2*jj][0] = tmp[0]; Bhf[2*jj][1] = tmp[1];
                Bhf[2*jj+1][0] = tmp[2]; Bhf[2*jj+1][1] = tmp[3];
                ldsm_x4t(off + 4096, tmp);
                Blf[2*jj][0] = tmp[0]; Blf[2*jj][1] = tmp[1];
                Blf[2*jj+1][0] = tmp[2]; Blf[2*jj+1][1] = tmp[3];
            }
#pragma unroll
            for (int i = 0; i < 2; i++)
#pragma unroll
                for (int j = 0; j < 4; j++) {
                    mma_bf16(acc[i][j], Ahf[i], Bhf[j]);
                    mma_bf16(acc[i][j], Ahf[i], Blf[j]);
                    mma_bf16(acc[i][j], Alf[i], Bhf[j]);
                }
        }
        __syncthreads();
    }

    const int g = lane >> 2, tq = lane & 3;
#pragma unroll
    for (int i = 0; i < 2; i++) {
#pragma unroll
        for (int j = 0; j < 4; j++) {
            int row = m0 + wm*32 + i*16 + g;
            int col = n0 + wn*32 + j*8 + tq*2;
            *(float2*)(Cm + (size_t)row*Cc + col) =
                make_float2(acc[i][j][0], acc[i][j][1]);
            *(float2*)(Cm + (size_t)(row + 8)*Cc + col) =
                make_float2(acc[i][j][2], acc[i][j][3]);
        }
    }
}

__global__ __launch_bounds__(256, 2) void k_gemm_qkv()
{
    int z = blockIdx.z;
    float* C = (z == 0) ? s_yq : (z == 1) ? s_yk : s_yv;
    gemm_cp(a_hi[z], a_lo[z], w_hi[z], w_lo[z], C);
}

__global__ __launch_bounds__(256, 2) void k_gemm_o(float* __restrict__ out)
{
    gemm_cp(o_hi, o_lo, w_hi[3], w_lo[3], out);
}

// ---------------- LN (+RoPE) into head layout ----------------
__global__ __launch_bounds__(256) void k_lnqkv(
    const float* __restrict__ gr, const float* __restrict__ br_,
    const float* __restrict__ gk, const float* __restrict__ bk_,
    const float* __restrict__ gv, const float* __restrict__ bv_,
    const float* __restrict__ cosT, const float* __restrict__ sinT)
{
    int mode = blockIdx.y;
    const float* Y; const float* g; const float* bbv; float* out;
    if (mode == 0)      { Y = s_yq; g = gr; bbv = br_; out = s_qh; }
    else if (mode == 1) { Y = s_yk; g = gk; bbv = bk_; out = s_kh; }
    else                { Y = s_yv; g = gv; bbv = bv_; out = s_vh; }
    int row = blockIdx.x;
    int t = row & (Tt - 1), b = row >> 10;
    __shared__ float srow[Cc];
    __shared__ float red[64];
    const float* yr = Y + (size_t)row*Cc;
    float sum = 0.f, sq = 0.f, vals[8];
#pragma unroll
    for (int k = 0; k < 8; k++) {
        float v = yr[threadIdx.x + k*256];
        vals[k] = v; sum += v; sq = fmaf(v, v, sq);
    }
#pragma unroll
    for (int o = 16; o; o >>= 1) {
        sum += __shfl_xor_sync(0xffffffffu, sum, o);
        sq  += __shfl_xor_sync(0xffffffffu, sq,  o);
    }
    int w = threadIdx.x >> 5;
    if ((threadIdx.x & 31) == 0) { red[w] = sum; red[32 + w] = sq; }
    __syncthreads();
    if (threadIdx.x < 32) {
        float s1 = (threadIdx.x < 8) ? red[threadIdx.x] : 0.f;
        float s2 = (threadIdx.x < 8) ? red[32 + threadIdx.x] : 0.f;
#pragma unroll
        for (int o = 4; o; o >>= 1) {
            s1 += __shfl_xor_sync(0xffffffffu, s1, o);
            s2 += __shfl_xor_sync(0xffffffffu, s2, o);
        }
        if (threadIdx.x == 0) { red[0] = s1; red[32] = s2; }
    }
    __syncthreads();
    float mu  = red[0]  * (1.f/Cc);
    float var = red[32] * (1.f/Cc) - mu*mu;
    float inv = rsqrtf(var + 1e-5f);
#pragma unroll
    for (int k = 0; k < 8; k++) {
        int c = threadIdx.x + k*256;
        srow[c] = (vals[k] - mu)*inv*g[c] + bbv[c];
    }
    __syncthreads();
#pragma unroll
    for (int k = 0; k < 8; k++) {
        int c = threadIdx.x + k*256;
        int h = c >> 6, d = c & 63;
        float o;
        if (mode == 2) { o = srow[c]; }
        else if (d < 32) {
            float cc = cosT[t*32 + d], ss = sinT[t*32 + d];
            o = srow[c]*cc - srow[c + 32]*ss;
        } else {
            int d2 = d - 32;
            float cc = cosT[t*32 + d2], ss = sinT[t*32 + d2];
            o = srow[c - 32]*ss + srow[c]*cc;
        }
        out[(((size_t)(b*Hh + h)*Tt + t) << 6) + d] = o;
    }
}

// ---------------- LN of attention output (writes bf16 hi/lo) -------------
__global__ __launch_bounds__(256) void k_lnplain(
    const float* __restrict__ gx, const float* __restrict__ bx)
{
    int row = blockIdx.x;
    __shared__ float red[64];
    const float* yr = s_att + (size_t)row*Cc;
    float sum = 0.f, sq = 0.f, vals[8];
#pragma unroll
    for (int k = 0; k < 8; k++) {
        float v = yr[threadIdx.x + k*256];
        vals[k] = v; sum += v; sq = fmaf(v, v, sq);
    }
#pragma unroll
    for (int o = 16; o; o >>= 1) {
        sum += __shfl_xor_sync(0xffffffffu, sum, o);
        sq  += __shfl_xor_sync(0xffffffffu, sq,  o);
    }
    int w = threadIdx.x >> 5;
    if ((threadIdx.x & 31) == 0) { red[w] = sum; red[32 + w] = sq; }
    __syncthreads();
    if (threadIdx.x < 32) {
        float s1 = (threadIdx.x < 8) ? red[threadIdx.x] : 0.f;
        float s2 = (threadIdx.x < 8) ? red[32 + threadIdx.x] : 0.f;
#pragma unroll
        for (int o = 4; o; o >>= 1) {
            s1 += __shfl_xor_sync(0xffffffffu, s1, o);
            s2 += __shfl_xor_sync(0xffffffffu, s2, o);
        }
        if (threadIdx.x == 0) { red[0] = s1; red[32] = s2; }
    }
    __syncthreads();
    float mu  = red[0]  * (1.f/Cc);
    float var = red[32] * (1.f/Cc) - mu*mu;
    float inv = rsqrtf(var + 1e-5f);
    size_t rb = (size_t)row*Cc;
#pragma unroll
    for (int k = 0; k < 8; k++) {
        int c = threadIdx.x + k*256;
        float v = (vals[k] - mu)*inv*gx[c] + bx[c];
        __nv_bfloat16 hv = __float2bfloat16_rn(v);
        o_hi[rb + c] = hv;
        o_lo[rb + c] = __float2bfloat16_rn(v - __bfloat162float(hv));
    }
}

// ======== causal flash attention, tensor cores, 3x-bf16 split ========
__global__ __launch_bounds__(128) void k_attn_tc()
{
    __shared__ __align__(16) __nv_bfloat16 sQ[2][4096];
    __shared__ __align__(16) __nv_bfloat16 sK[2][4096];
    __shared__ __align__(16) __nv_bfloat16 sV[2][4096];

    const int qt  = (int)gridDim.x - 1 - (int)blockIdx.x;
    const int bh  = blockIdx.y;
    const int b   = bh >> 5, h = bh & 31;
    const int tid = threadIdx.x, lane = tid & 31, w = tid >> 5;
    const int q0  = qt * 64;
    const float* Qg = s_qh + (size_t)bh*Tt*64;
    const float* Kg = s_kh + (size_t)bh*Tt*64;
    const float* Vg = s_vh + (size_t)bh*Tt*64;
    const uint32_t bQ0 = cvta_sm(sQ[0]), bQ1 = cvta_sm(sQ[1]);
    const uint32_t bK0 = cvta_sm(sK[0]), bK1 = cvta_sm(sK[1]);
    const uint32_t bV0 = cvta_sm(sV[0]), bV1 = cvta_sm(sV[1]);

#pragma unroll
    for (int i = 0; i < 4; i++) {
        int seg = tid + i*128;
        int row = seg >> 3, ch = seg & 7;
        const float* src = Qg + (size_t)(q0 + row)*64 + ch*8;
        float4 v0 = *(const float4*)src, v1 = *(const float4*)(src + 4);
        float r0,r1,r2,r3,r4,r5,r6,r7;
        uint4 hi, lo;
        hi.x = pack_hi2(v0.x, v0.y, r0, r1);
        hi.y = pack_hi2(v0.z, v0.w, r2, r3);
        hi.z = pack_hi2(v1.x, v1.y, r4, r5);
        hi.w = pack_hi2(v1.z, v1.w, r6, r7);
        lo.x = packbf(r0, r1); lo.y = packbf(r2, r3);
        lo.z = packbf(r4, r5); lo.w = packbf(r6, r7);
        int off = (row*8 + (ch ^ (row & 7)))*8;
        *(uint4*)&sQ[0][off] = hi;
        *(uint4*)&sQ[1][off] = lo;
    }
    __syncthreads();

    uint32_t qh[4][4], ql[4][4];
    const int g8 = lane >> 3, rr8 = lane & 7;
#pragma unroll
    for (int kk = 0; kk < 4; kk++) {
        int row = w*16 + (g8 & 1)*8 + rr8;
        int ch  = kk*2 + (g8 >> 1);
        uint32_t off = (uint32_t)(row*8 + (ch ^ (row & 7)))*16;
        ldsm_x4(bQ0 + off, qh[kk]);
        ldsm_x4(bQ1 + off, ql[kk]);
    }

    float o[8][4];
#pragma unroll
    for (int j = 0; j < 8; j++)
#pragma unroll
        for (int e = 0; e < 4; e++) o[j][e] = 0.f;
    float m0 = -1e30f, m1 = -1e30f, l0 = 0.f, l1 = 0.f;

    for (int kt = 0; kt <= qt; kt++) {
        int s0 = kt * 64;
        float4 kvreg[8][2];
#pragma unroll
        for (int i = 0; i < 4; i++) {
            int seg = tid + i*128;
            int row = seg >> 3, ch = seg & 7;
            const float* ks = Kg + (size_t)(s0 + row)*64 + ch*8;
            const float* vs = Vg + (size_t)(s0 + row)*64 + ch*8;
            kvreg[i][0]   = *(const float4*)ks; kvreg[i][1]   = *(const float4*)(ks + 4);
            kvreg[i+4][0] = *(const float4*)vs; kvreg[i+4][1] = *(const float4*)(vs + 4);
        }
        __syncthreads();
#pragma unroll
        for (int i = 0; i < 8; i++) {
            int seg = tid + (i & 3)*128;
            int row = seg >> 3, ch = seg & 7;
            int off = (row*8 + (ch ^ (row & 7)))*8;
            float r0,r1,r2,r3,r4,r5,r6,r7;
            uint4 hi, lo;
            hi.x = pack_hi2(kvreg[i][0].x, kvreg[i][0].y, r0, r1);
            hi.y = pack_hi2(kvreg[i][0].z, kvreg[i][0].w, r2, r3);
            hi.z = pack_hi2(kvreg[i][1].x, kvreg[i][1].y, r4, r5);
            hi.w = pack_hi2(kvreg[i][1].z, kvreg[i][1].w, r6, r7);
            lo.x = packbf(r0, r1); lo.y = packbf(r2, r3);
            lo.z = packbf(r4, r5); lo.w = packbf(r6, r7);
            __nv_bfloat16* dh = (i < 4) ? sK[0] : sV[0];
            __nv_bfloat16* dl = (i < 4) ? sK[1] : sV[1];
            *(uint4*)&dh[off] = hi;
            *(uint4*)&dl[off] = lo;
        }
        __syncthreads();

        float c[8][4];
#pragma unroll
        for (int j = 0; j < 8; j++)
#pragma unroll
            for (int e = 0; e < 4; e++) c[j][e] = 0.f;
#pragma unroll
        for (int kk = 0; kk < 4; kk++) {
            uint32_t kbh[4][4], kbl[4][4];
#pragma unroll
            for (int u = 0; u < 4; u++) {
                int row = u*16 + (g8 >> 1)*8 + rr8;
                int ch  = kk*2 + (g8 & 1);
                uint32_t off = (uint32_t)(row*8 + (ch ^ (row & 7)))*16;
                ldsm_x4(bK0 + off, kbh[u]);
                ldsm_x4(bK1 + off, kbl[u]);
            }
#pragma unroll
            for (int u = 0; u < 4; u++) {
                mma_bf16(c[2*u],   qh[kk], &kbh[u][0]);
                mma_bf16(c[2*u],   qh[kk], &kbl[u][0]);
                mma_bf16(c[2*u],   ql[kk], &kbh[u][0]);
                mma_bf16(c[2*u+1], qh[kk], &kbh[u][2]);
                mma_bf16(c[2*u+1], qh[kk], &kbl[u][2]);
                mma_bf16(c[2*u+1], ql[kk], &kbh[u][2]);
            }
        }
        const int rl0 = w*16 + (lane >> 2);
#pragma unroll
        for (int j = 0; j < 8; j++)
#pragma unroll
            for (int e = 0; e < 4; e++) c[j][e] *= 0.125f;
        if (kt == qt) {
#pragma unroll
            for (int j = 0; j < 8; j++) {
                int col = j*8 + 2*(lane & 3);
                if (col     > rl0)     c[j][0] = -1e30f;
                if (col + 1 > rl0)     c[j][1] = -1e30f;
                if (col     > rl0 + 8) c[j][2] = -1e30f;
                if (col + 1 > rl0 + 8) c[j][3] = -1e30f;
            }
        }
        float mx0 = -1e30f, mx1 = -1e30f;
#pragma unroll
        for (int j = 0; j < 8; j++) {
            mx0 = fmaxf(mx0, fmaxf(c[j][0], c[j][1]));
            mx1 = fmaxf(mx1, fmaxf(c[j][2], c[j][3]));
        }
        mx0 = fmaxf(mx0, __shfl_xor_sync(0xffffffffu, mx0, 1));
        mx0 = fmaxf(mx0, __shfl_xor_sync(0xffffffffu, mx0, 2));
        mx1 = fmaxf(mx1, __shfl_xor_sync(0xffffffffu, mx1, 1));
        mx1 = fmaxf(mx1, __shfl_xor_sync(0xffffffffu, mx1, 2));
        float mn0 = fmaxf(m0, mx0), mn1 = fmaxf(m1, mx1);
        float a0 = __expf(m0 - mn0), a1 = __expf(m1 - mn1);
        m0 = mn0; m1 = mn1;

        uint32_t ph[4][4], pl[4][4];
        float rs0 = 0.f, rs1 = 0.f;
#pragma unroll
        for (int t = 0; t < 4; t++) {
            float p00 = __expf(c[2*t][0]   - mn0), p01 = __expf(c[2*t][1]   - mn0);
            float p02 = __expf(c[2*t][2]   - mn1), p03 = __expf(c[2*t][3]   - mn1);
            float p10 = __expf(c[2*t+1][0] - mn0), p11 = __expf(c[2*t+1][1] - mn0);
            float p12 = __expf(c[2*t+1][2] - mn1), p13 = __expf(c[2*t+1][3] - mn1);
            rs0 += p00 + p01 + p10 + p11;
            rs1 += p02 + p03 + p12 + p13;
            float e0, e1;
            ph[t][0] = pack_hi2(p00, p01, e0, e1); pl[t][0] = packbf(e0, e1);
            ph[t][1] = pack_hi2(p02, p03, e0, e1); pl[t][1] = packbf(e0, e1);
            ph[t][2] = pack_hi2(p10, p11, e0, e1); pl[t][2] = packbf(e0, e1);
            ph[t][3] = pack_hi2(p12, p13, e0, e1); pl[t][3] = packbf(e0, e1);
        }
        rs0 += __shfl_xor_sync(0xffffffffu, rs0, 1);
        rs0 += __shfl_xor_sync(0xffffffffu, rs0, 2);
        rs1 += __shfl_xor_sync(0xffffffffu, rs1, 1);
        rs1 += __shfl_xor_sync(0xffffffffu, rs1, 2);
        l0 = l0*a0 + rs0;
        l1 = l1*a1 + rs1;
#pragma unroll
        for (int j = 0; j < 8; j++) {
            o[j][0] *= a0; o[j][1] *= a0;
            o[j][2] *= a1; o[j][3] *= a1;
        }
#pragma unroll
        for (int t = 0; t < 4; t++) {
#pragma unroll
            for (int u = 0; u < 4; u++) {
                int row = t*16 + (g8 & 1)*8 + rr8;
                int ch  = u*2 + (g8 >> 1);
                uint32_t off = (uint32_t)(row*8 + (ch ^ (row & 7)))*16;
                uint32_t vh_[4], vl_[4];
                ldsm_x4t(bV0 + off, vh_);
                ldsm_x4t(bV1 + off, vl_);
                mma_bf16(o[2*u],   ph[t], &vh_[0]);
                mma_bf16(o[2*u],   pl[t], &vh_[0]);
                mma_bf16(o[2*u],   ph[t], &vl_[0]);
                mma_bf16(o[2*u+1], ph[t], &vh_[2]);
                mma_bf16(o[2*u+1], pl[t], &vh_[2]);
                mma_bf16(o[2*u+1], ph[t], &vl_[2]);
            }
        }
    }

    float inv0 = 1.f / l0, inv1 = 1.f / l1;
    int rg0 = q0 + w*16 + (lane >> 2);
    float* base0 = s_att + (size_t)(b*Tt + rg0)*Cc + h*64;
    float* base1 = base0 + (size_t)8*Cc;
#pragma unroll
    for (int j = 0; j < 8; j++) {
        int colo = j*8 + 2*(lane & 3);
        *(float2*)(base0 + colo) = make_float2(o[j][0]*inv0, o[j][1]*inv0);
        *(float2*)(base1 + colo) = make_float2(o[j][2]*inv1, o[j][3]*inv1);
    }
}

// ---------------- launch ----------------
extern "C" void kernel_launch(void* const* d_in, const int* in_sizes, int n_in,
                              void* d_out, int out_size)
{
    (void)in_sizes; (void)n_in; (void)out_size;
    const float* x     = (const float*)d_in[0];
    const float* shift = (const float*)d_in[1];
    const float* maa_x = (const float*)d_in[2];
    const float* maa_r = (const float*)d_in[3];
    const float* maa_k = (const float*)d_in[4];
    const float* maa_v = (const float*)d_in[5];
    const float* w1    = (const float*)d_in[6];
    const float* w2    = (const float*)d_in[7];
    const float* Wq    = (const float*)d_in[8];
    const float* Wk    = (const float*)d_in[9];
    const float* Wv    = (const float*)d_in[10];
    const float* Wo    = (const float*)d_in[11];
    const float* g_r   = (const float*)d_in[12];
    const float* b_r   = (const float*)d_in[13];
    const float* g_k   = (const float*)d_in[14];
    const float* b_k   = (const float*)d_in[15];
    const float* g_v   = (const float*)d_in[16];
    const float* b_v   = (const float*)d_in[17];
    const float* g_x   = (const float*)d_in[18];
    const float* b_x   = (const float*)d_in[19];
    const float* cosT  = (const float*)d_in[20];
    const float* sinT  = (const float*)d_in[21];
    float* out = (float*)d_out;

    cudaFuncSetAttribute(k_gemm_qkv, cudaFuncAttributeMaxDynamicSharedMemorySize,
                         GEMM_SMEM_BYTES);
    cudaFuncSetAttribute(k_gemm_o, cudaFuncAttributeMaxDynamicSharedMemorySize,
                         GEMM_SMEM_BYTES);

    k_wcvt<<<dim3(Cc*Cc/1024, 4), 256>>>(Wq, Wk, Wv, Wo);
    k_lora1<<<NT/16, 96>>>(x, shift, maa_x, w1);
    k_mix<<<dim3(Cc/64, NT/16), 256>>>(x, shift, w2, maa_r, maa_k, maa_v);
    k_gemm_qkv<<<dim3(Cc/64, 16, 3), 256, GEMM_SMEM_BYTES>>>();
    k_lnqkv<<<dim3(NT, 3), 256>>>(g_r, b_r, g_k, b_k, g_v, b_v, cosT, sinT);
    k_attn_tc<<<dim3(16, Bb*Hh), 128>>>();
    k_lnplain<<<NT, 256>>>(g_x, b_x);
    k_gemm_o<<<dim3(Cc/64, 16), 256, GEMM_SMEM_BYTES>>>(out);
}

// round 12
// speedup vs baseline: 1.0016x; 1.0016x over previous
#include <cuda_runtime.h>
#include <cuda_bf16.h>
#include <math.h>
#include <stdint.h>

#define Bb 2
#define Tt 1024
#define Cc 2048
#define Hh 32
#define Dd 64
#define NT (Bb*Tt)
#define L3 96

// ---------------- scratch ----------------
__device__ __align__(16) float s_h [NT*L3];
__device__ __align__(16) float s_yq[NT*Cc];
__device__ __align__(16) float s_yk[NT*Cc];
__device__ __align__(16) float s_yv[NT*Cc];
__device__ __align__(16) float s_att[NT*Cc];

// bf16 hi/lo planes
__device__ __align__(16) __nv_bfloat16 a_hi[3][NT*Cc];   // xr, xk, xv
__device__ __align__(16) __nv_bfloat16 a_lo[3][NT*Cc];
__device__ __align__(16) __nv_bfloat16 o_hi[NT*Cc];      // ln(attn out)
__device__ __align__(16) __nv_bfloat16 o_lo[NT*Cc];
__device__ __align__(16) __nv_bfloat16 w_hi[4][Cc*Cc];   // Wq, Wk, Wv, Wo
__device__ __align__(16) __nv_bfloat16 w_lo[4][Cc*Cc];
// head-layout q/k/v planes [B*H][T][64]
__device__ __align__(16) __nv_bfloat16 qp_hi[NT*Cc];
__device__ __align__(16) __nv_bfloat16 qp_lo[NT*Cc];
__device__ __align__(16) __nv_bfloat16 kp_hi[NT*Cc];
__device__ __align__(16) __nv_bfloat16 kp_lo[NT*Cc];
__device__ __align__(16) __nv_bfloat16 vp_hi[NT*Cc];
__device__ __align__(16) __nv_bfloat16 vp_lo[NT*Cc];

// ============ helpers ============
__device__ __forceinline__ uint32_t cvta_sm(const void* p) {
    return (uint32_t)__cvta_generic_to_shared(p);
}
__device__ __forceinline__ void ldsm_x4(uint32_t addr, uint32_t* r) {
    asm volatile("ldmatrix.sync.aligned.m8n8.x4.shared.b16 {%0,%1,%2,%3},[%4];"
        : "=r"(r[0]), "=r"(r[1]), "=r"(r[2]), "=r"(r[3]) : "r"(addr));
}
__device__ __forceinline__ void ldsm_x4t(uint32_t addr, uint32_t* r) {
    asm volatile("ldmatrix.sync.aligned.m8n8.x4.trans.shared.b16 {%0,%1,%2,%3},[%4];"
        : "=r"(r[0]), "=r"(r[1]), "=r"(r[2]), "=r"(r[3]) : "r"(addr));
}
__device__ __forceinline__ void mma_bf16(float* d, const uint32_t* a, const uint32_t* b) {
    asm volatile(
        "mma.sync.aligned.m16n8k16.row.col.f32.bf16.bf16.f32 "
        "{%0,%1,%2,%3},{%4,%5,%6,%7},{%8,%9},{%0,%1,%2,%3};"
        : "+f"(d[0]), "+f"(d[1]), "+f"(d[2]), "+f"(d[3])
        : "r"(a[0]), "r"(a[1]), "r"(a[2]), "r"(a[3]), "r"(b[0]), "r"(b[1]));
}
__device__ __forceinline__ uint32_t packbf(float x, float y) {
    __nv_bfloat162 h = __floats2bfloat162_rn(x, y);
    return *(uint32_t*)&h;
}
__device__ __forceinline__ uint32_t pack_hi2(float x, float y, float& rx, float& ry) {
    __nv_bfloat16 hx = __float2bfloat16_rn(x), hy = __float2bfloat16_rn(y);
    rx = x - __bfloat162float(hx);
    ry = y - __bfloat162float(hy);
    return ((uint32_t)*(uint16_t*)&hy << 16) | *(uint16_t*)&hx;
}
__device__ __forceinline__ void cp16(uint32_t dst, const void* src) {
    asm volatile("cp.async.cg.shared.global [%0], [%1], 16;" :: "r"(dst), "l"(src));
}
__device__ __forceinline__ void cp_commit() {
    asm volatile("cp.async.commit_group;" ::: "memory");
}
template<int N> __device__ __forceinline__ void cp_wait() {
    asm volatile("cp.async.wait_group %0;" :: "n"(N) : "memory");
}

// ---------------- weight pre-split ----------------
__global__ __launch_bounds__(256) void k_wcvt(
    const float* __restrict__ Wq, const float* __restrict__ Wk,
    const float* __restrict__ Wv, const float* __restrict__ Wo)
{
    int m = blockIdx.y;
    const float* src = (m == 0) ? Wq : (m == 1) ? Wk : (m == 2) ? Wv : Wo;
    size_t e = ((size_t)blockIdx.x * 256 + threadIdx.x) * 4;
    float4 v = *(const float4*)(src + e);
    float r0,r1,r2,r3;
    uint2 hi, lo;
    hi.x = pack_hi2(v.x, v.y, r0, r1);
    hi.y = pack_hi2(v.z, v.w, r2, r3);
    lo.x = packbf(r0, r1);
    lo.y = packbf(r2, r3);
    *(uint2*)&w_hi[m][e] = hi;
    *(uint2*)&w_lo[m][e] = lo;
}

// ---------------- LoRA stage 1 (xx computed inline) ----------
__global__ __launch_bounds__(96) void k_lora1(
    const float* __restrict__ x, const float* __restrict__ shift,
    const float* __restrict__ maa_x, const float* __restrict__ w1)
{
    __shared__ float xs[16][128];
    int n0 = blockIdx.x * 16;
    int j  = threadIdx.x;
    float acc[16];
#pragma unroll
    for (int r = 0; r < 16; r++) acc[r] = 0.f;
    for (int k0 = 0; k0 < Cc; k0 += 128) {
        __syncthreads();
        for (int i = threadIdx.x; i < 16*128; i += 96) {
            int r = i >> 7, cc = i & 127;
            int row = n0 + r, c = k0 + cc;
            int t = row & (Tt - 1), b = row >> 10;
            float xv = x[(size_t)row*Cc + c];
            float xp = (t == 0) ? shift[b*Cc + c] : x[(size_t)(row-1)*Cc + c];
            xs[r][cc] = fmaf(xp - xv, maa_x[c], xv);
        }
        __syncthreads();
        for (int k = 0; k < 128; k++) {
            float wv = w1[(k0 + k)*L3 + j];
#pragma unroll
            for (int r = 0; r < 16; r++) acc[r] = fmaf(xs[r][k], wv, acc[r]);
        }
    }
#pragma unroll
    for (int r = 0; r < 16; r++) s_h[(n0 + r)*L3 + j] = tanhf(acc[r]);
}

// ---------------- LoRA stage 2 + mixing ----------
__global__ __launch_bounds__(256) void k_mix(
    const float* __restrict__ x, const float* __restrict__ shift,
    const float* __restrict__ w2,
    const float* __restrict__ maa_r, const float* __restrict__ maa_k,
    const float* __restrict__ maa_v)
{
    __shared__ float w2s[96][64];
    __shared__ float hs[16][96];
    int c0 = blockIdx.x * 64;
    int n0 = blockIdx.y * 16;
    int tid = threadIdx.x;
    for (int i = tid; i < 96*64; i += 256) {
        int rr = i >> 6, cc = i & 63;
        w2s[rr][cc] = w2[rr*Cc + c0 + cc];
    }
    for (int i = tid; i < 16*96; i += 256) {
        int rr = i / 96, jj = i % 96;
        hs[rr][jj] = s_h[(n0 + rr)*L3 + jj];
    }
    __syncthreads();
    int col = tid & 63, rg = tid >> 6;
    int c = c0 + col;
    float ar = maa_r[c], ak = maa_k[c], av = maa_v[c];
#pragma unroll
    for (int rr = 0; rr < 4; rr++) {
        int r = rg*4 + rr;
        float m0 = 0.f, m1 = 0.f, m2 = 0.f;
#pragma unroll
        for (int i = 0; i < 32; i++) {
            m0 = fmaf(hs[r][i],      w2s[i][col],      m0);
            m1 = fmaf(hs[r][32 + i], w2s[32 + i][col], m1);
            m2 = fmaf(hs[r][64 + i], w2s[64 + i][col], m2);
        }
        int row = n0 + r;
        int t = row & (Tt - 1), b = row >> 10;
        size_t idx = (size_t)row*Cc + c;
        float xf = x[idx];
        float xp = (t == 0) ? shift[b*Cc + c] : x[idx - Cc];
        float dxf = xp - xf;
        float vr = fmaf(dxf, ar + m0, xf);
        float vk = fmaf(dxf, ak + m1, xf);
        float vv = fmaf(dxf, av + m2, xf);
        __nv_bfloat16 hr = __float2bfloat16_rn(vr);
        __nv_bfloat16 hk = __float2bfloat16_rn(vk);
        __nv_bfloat16 hv = __float2bfloat16_rn(vv);
        a_hi[0][idx] = hr; a_lo[0][idx] = __float2bfloat16_rn(vr - __bfloat162float(hr));
        a_hi[1][idx] = hk; a_lo[1][idx] = __float2bfloat16_rn(vk - __bfloat162float(hk));
        a_hi[2][idx] = hv; a_lo[2][idx] = __float2bfloat16_rn(vv - __bfloat162float(hv));
    }
}

// ============ bf16 3-term GEMM, CTA tile 128x64, 3-stage cp.async ============
#define GEMM_SMEM_BYTES 73728

__device__ __forceinline__ void gemm_cp(
    const __nv_bfloat16* __restrict__ Ah, const __nv_bfloat16* __restrict__ Al,
    const __nv_bfloat16* __restrict__ Bh, const __nv_bfloat16* __restrict__ Bl,
    float* __restrict__ Cm)
{
    extern __shared__ __align__(16) unsigned char smema[];
    const uint32_t sm0 = cvta_sm(smema);
    const int tid = threadIdx.x, lane = tid & 31, wid = tid >> 5;
    const int wm = wid >> 1, wn = wid & 1;
    const int m0 = blockIdx.y * 128, n0 = blockIdx.x * 64;

    auto issue = [&](int kt, int s) {
        uint32_t SS = sm0 + s*24576;
#pragma unroll
        for (int t = 0; t < 4; t++) {
            int idx = tid + t*256;
            int term = idx >> 9, ksub = (idx >> 8) & 1;
            int row = (idx >> 1) & 127, ch = idx & 1;
            const __nv_bfloat16* src = (term ? Al : Ah)
                + (size_t)(m0 + row)*Cc + kt*32 + ksub*16 + ch*8;
            uint32_t dst = SS + term*8192 + ksub*4096 + row*32
                         + ((ch ^ ((row >> 2) & 1))*16);
            cp16(dst, src);
        }
#pragma unroll
        for (int t = 0; t < 2; t++) {
            int idx = tid + t*256;
            int term = idx >> 8, kr = (idx >> 3) & 31, ch = idx & 7;
            const __nv_bfloat16* src = (term ? Bl : Bh)
                + (size_t)(kt*32 + kr)*Cc + n0 + ch*8;
            uint32_t dst = SS + 16384 + term*4096 + kr*128 + ((ch ^ (kr & 7))*16);
            cp16(dst, src);
        }
        cp_commit();
    };

    float acc[2][4][4];
#pragma unroll
    for (int i = 0; i < 2; i++)
#pragma unroll
        for (int j = 0; j < 4; j++)
#pragma unroll
            for (int e = 0; e < 4; e++) acc[i][j][e] = 0.f;

    const int rlA = lane & 15;
    const int selA = lane >> 4;
    const int krB = ((lane >> 3) & 1)*8 + (lane & 7);
    const int ncB = lane >> 4;

    issue(0, 0);
    issue(1, 1);
    const int NKT = Cc / 32;
    for (int kt = 0; kt < NKT; kt++) {
        if (kt + 1 < NKT) cp_wait<1>(); else cp_wait<0>();
        __syncthreads();
        if (kt + 2 < NKT) issue(kt + 2, (kt + 2) % 3);
        uint32_t SS = sm0 + (kt % 3)*24576;
#pragma unroll
        for (int ksub = 0; ksub < 2; ksub++) {
            uint32_t Ahf[2][4], Alf[2][4], Bhf[4][2], Blf[4][2];
#pragma unroll
            for (int i = 0; i < 2; i++) {
                int row = wm*32 + i*16 + rlA;
                uint32_t off = SS + ksub*4096 + row*32
                             + ((selA ^ ((row >> 2) & 1))*16);
                ldsm_x4(off, Ahf[i]);
                ldsm_x4(off + 8192, Alf[i]);
            }
#pragma unroll
            for (int jj = 0; jj < 2; jj++) {
                int kr = ksub*16 + krB;
                int nchunk = wn*4 + jj*2 + ncB;
                uint32_t off = SS + 16384 + kr*128 + ((nchunk ^ (kr & 7))*16);
                uint32_t tmp[4];
                ldsm_x4t(off, tmp);
                Bhf[2*jj][0] = tmp[0]; Bhf[2*jj][1] = tmp[1];
                Bhf[2*jj+1][0] = tmp[2]; Bhf[2*jj+1][1] = tmp[3];
                ldsm_x4t(off + 4096, tmp);
                Blf[2*jj][0] = tmp[0]; Blf[2*jj][1] = tmp[1];
                Blf[2*jj+1][0] = tmp[2]; Blf[2*jj+1][1] = tmp[3];
            }
#pragma unroll
            for (int i = 0; i < 2; i++)
#pragma unroll
                for (int j = 0; j < 4; j++) {
                    mma_bf16(acc[i][j], Ahf[i], Bhf[j]);
                    mma_bf16(acc[i][j], Ahf[i], Blf[j]);
                    mma_bf16(acc[i][j], Alf[i], Bhf[j]);
                }
        }
    }

    const int g = lane >> 2, tq = lane & 3;
#pragma unroll
    for (int i = 0; i < 2; i++) {
#pragma unroll
        for (int j = 0; j < 4; j++) {
            int row = m0 + wm*32 + i*16 + g;
            int col = n0 + wn*32 + j*8 + tq*2;
            *(float2*)(Cm + (size_t)row*Cc + col) =
                make_float2(acc[i][j][0], acc[i][j][1]);
            *(float2*)(Cm + (size_t)(row + 8)*Cc + col) =
                make_float2(acc[i][j][2], acc[i][j][3]);
        }
    }
}

__global__ __launch_bounds__(256, 2) void k_gemm_qkv()
{
    int z = blockIdx.z;
    float* C = (z == 0) ? s_yq : (z == 1) ? s_yk : s_yv;
    gemm_cp(a_hi[z], a_lo[z], w_hi[z], w_lo[z], C);
}

__global__ __launch_bounds__(256, 2) void k_gemm_o(float* __restrict__ out)
{
    gemm_cp(o_hi, o_lo, w_hi[3], w_lo[3], out);
}

// ---------------- LN (+RoPE) into head-layout bf16 hi/lo planes -------------
__global__ __launch_bounds__(256) void k_lnqkv(
    const float* __restrict__ gr, const float* __restrict__ br_,
    const float* __restrict__ gk, const float* __restrict__ bk_,
    const float* __restrict__ gv, const float* __restrict__ bv_,
    const float* __restrict__ cosT, const float* __restrict__ sinT)
{
    int mode = blockIdx.y;
    const float* Y; const float* g; const float* bbv;
    __nv_bfloat16 *phi, *plo;
    if (mode == 0)      { Y = s_yq; g = gr; bbv = br_; phi = qp_hi; plo = qp_lo; }
    else if (mode == 1) { Y = s_yk; g = gk; bbv = bk_; phi = kp_hi; plo = kp_lo; }
    else                { Y = s_yv; g = gv; bbv = bv_; phi = vp_hi; plo = vp_lo; }
    int row = blockIdx.x;
    int t = row & (Tt - 1), b = row >> 10;
    __shared__ float srow[Cc];
    __shared__ float red[64];
    const float* yr = Y + (size_t)row*Cc;
    float sum = 0.f, sq = 0.f, vals[8];
#pragma unroll
    for (int k = 0; k < 8; k++) {
        float v = yr[threadIdx.x + k*256];
        vals[k] = v; sum += v; sq = fmaf(v, v, sq);
    }
#pragma unroll
    for (int o = 16; o; o >>= 1) {
        sum += __shfl_xor_sync(0xffffffffu, sum, o);
        sq  += __shfl_xor_sync(0xffffffffu, sq,  o);
    }
    int w = threadIdx.x >> 5;
    if ((threadIdx.x & 31) == 0) { red[w] = sum; red[32 + w] = sq; }
    __syncthreads();
    if (threadIdx.x < 32) {
        float s1 = (threadIdx.x < 8) ? red[threadIdx.x] : 0.f;
        float s2 = (threadIdx.x < 8) ? red[32 + threadIdx.x] : 0.f;
#pragma unroll
        for (int o = 4; o; o >>= 1) {
            s1 += __shfl_xor_sync(0xffffffffu, s1, o);
            s2 += __shfl_xor_sync(0xffffffffu, s2, o);
        }
        if (threadIdx.x == 0) { red[0] = s1; red[32] = s2; }
    }
    __syncthreads();
    float mu  = red[0]  * (1.f/Cc);
    float var = red[32] * (1.f/Cc) - mu*mu;
    float inv = rsqrtf(var + 1e-5f);
#pragma unroll
    for (int k = 0; k < 8; k++) {
        int c = threadIdx.x + k*256;
        srow[c] = (vals[k] - mu)*inv*g[c] + bbv[c];
    }
    __syncthreads();
#pragma unroll
    for (int k = 0; k < 8; k++) {
        int c = threadIdx.x + k*256;
        int h = c >> 6, d = c & 63;
        float o;
        if (mode == 2) { o = srow[c]; }
        else if (d < 32) {
            float cc = cosT[t*32 + d], ss = sinT[t*32 + d];
            o = srow[c]*cc - srow[c + 32]*ss;
        } else {
            int d2 = d - 32;
            float cc = cosT[t*32 + d2], ss = sinT[t*32 + d2];
            o = srow[c - 32]*ss + srow[c]*cc;
        }
        size_t off = (((size_t)(b*Hh + h)*Tt + t) << 6) + d;
        __nv_bfloat16 hv = __float2bfloat16_rn(o);
        phi[off] = hv;
        plo[off] = __float2bfloat16_rn(o - __bfloat162float(hv));
    }
}

// ---------------- LN of attention output (writes bf16 hi/lo) -------------
__global__ __launch_bounds__(256) void k_lnplain(
    const float* __restrict__ gx, const float* __restrict__ bx)
{
    int row = blockIdx.x;
    __shared__ float red[64];
    const float* yr = s_att + (size_t)row*Cc;
    float sum = 0.f, sq = 0.f, vals[8];
#pragma unroll
    for (int k = 0; k < 8; k++) {
        float v = yr[threadIdx.x + k*256];
        vals[k] = v; sum += v; sq = fmaf(v, v, sq);
    }
#pragma unroll
    for (int o = 16; o; o >>= 1) {
        sum += __shfl_xor_sync(0xffffffffu, sum, o);
        sq  += __shfl_xor_sync(0xffffffffu, sq,  o);
    }
    int w = threadIdx.x >> 5;
    if ((threadIdx.x & 31) == 0) { red[w] = sum; red[32 + w] = sq; }
    __syncthreads();
    if (threadIdx.x < 32) {
        float s1 = (threadIdx.x < 8) ? red[threadIdx.x] : 0.f;
        float s2 = (threadIdx.x < 8) ? red[32 + threadIdx.x] : 0.f;
#pragma unroll
        for (int o = 4; o; o >>= 1) {
            s1 += __shfl_xor_sync(0xffffffffu, s1, o);
            s2 += __shfl_xor_sync(0xffffffffu, s2, o);
        }
        if (threadIdx.x == 0) { red[0] = s1; red[32] = s2; }
    }
    __syncthreads();
    float mu  = red[0]  * (1.f/Cc);
    float var = red[32] * (1.f/Cc) - mu*mu;
    float inv = rsqrtf(var + 1e-5f);
    size_t rb = (size_t)row*Cc;
#pragma unroll
    for (int k = 0; k < 8; k++) {
        int c = threadIdx.x + k*256;
        float v = (vals[k] - mu)*inv*gx[c] + bx[c];
        __nv_bfloat16 hv = __float2bfloat16_rn(v);
        o_hi[rb + c] = hv;
        o_lo[rb + c] = __float2bfloat16_rn(v - __bfloat162float(hv));
    }
}

// ======== causal flash attention: cp.async pre-split tiles, 3x-bf16 ========
// dyn smem: Q hi/lo 16KB @0; stage s @16384+s*32768: Khi,Klo,Vhi,Vlo x 8KB
#define ATTN_SMEM_BYTES 81920

__global__ __launch_bounds__(128, 2) void k_attn_tc()
{
    extern __shared__ __align__(16) unsigned char asmem[];
    const uint32_t sb = cvta_sm(asmem);

    const int qt  = (int)gridDim.x - 1 - (int)blockIdx.x;
    const int bh  = blockIdx.y;
    const int b   = bh >> 5, h = bh & 31;
    const int tid = threadIdx.x, lane = tid & 31, w = tid >> 5;
    const int q0  = qt * 64;
    const size_t basebh = (size_t)bh*Tt*64;

    auto issueKV = [&](int kt2, int s) {
        uint32_t SS = sb + 16384 + s*32768;
        int s0 = kt2*64;
#pragma unroll
        for (int i = 0; i < 4; i++) {
            int idx = tid + i*128;
            int row = idx >> 3, ch = idx & 7;
            uint32_t o = (uint32_t)((row*8 + (ch ^ (row & 7)))*16);
            size_t src = basebh + (size_t)(s0 + row)*64 + ch*8;
            cp16(SS + o,         kp_hi + src);
            cp16(SS + 8192 + o,  kp_lo + src);
            cp16(SS + 16384 + o, vp_hi + src);
            cp16(SS + 24576 + o, vp_lo + src);
        }
        cp_commit();
    };

    // Q tile (hi/lo) via cp.async
    {
#pragma unroll
        for (int i = 0; i < 4; i++) {
            int idx = tid + i*128;
            int row = idx >> 3, ch = idx & 7;
            uint32_t o = (uint32_t)((row*8 + (ch ^ (row & 7)))*16);
            size_t src = basebh + (size_t)(q0 + row)*64 + ch*8;
            cp16(sb + o,        qp_hi + src);
            cp16(sb + 8192 + o, qp_lo + src);
        }
        cp_commit();
    }
    issueKV(0, 0);
    cp_wait<1>();          // Q complete
    __syncthreads();

    uint32_t qh[4][4], ql[4][4];
    const int g8 = lane >> 3, rr8 = lane & 7;
#pragma unroll
    for (int kk = 0; kk < 4; kk++) {
        int row = w*16 + (g8 & 1)*8 + rr8;
        int ch  = kk*2 + (g8 >> 1);
        uint32_t off = (uint32_t)(row*8 + (ch ^ (row & 7)))*16;
        ldsm_x4(sb + off, qh[kk]);
        ldsm_x4(sb + 8192 + off, ql[kk]);
    }

    float o[8][4];
#pragma unroll
    for (int j = 0; j < 8; j++)
#pragma unroll
        for (int e = 0; e < 4; e++) o[j][e] = 0.f;
    float m0 = -1e30f, m1 = -1e30f, l0 = 0.f, l1 = 0.f;

    for (int kt = 0; kt <= qt; kt++) {
        if (kt + 1 <= qt) { issueKV(kt + 1, (kt + 1) & 1); cp_wait<1>(); }
        else              { cp_wait<0>(); }
        __syncthreads();
        const uint32_t SK = sb + 16384 + (kt & 1)*32768;
        const uint32_t SV = SK + 16384;

        float c[8][4];
#pragma unroll
        for (int j = 0; j < 8; j++)
#pragma unroll
            for (int e = 0; e < 4; e++) c[j][e] = 0.f;
#pragma unroll
        for (int kk = 0; kk < 4; kk++) {
            uint32_t kbh[4][4], kbl[4][4];
#pragma unroll
            for (int u = 0; u < 4; u++) {
                int row = u*16 + (g8 >> 1)*8 + rr8;
                int ch  = kk*2 + (g8 & 1);
                uint32_t off = (uint32_t)(row*8 + (ch ^ (row & 7)))*16;
                ldsm_x4(SK + off, kbh[u]);
                ldsm_x4(SK + 8192 + off, kbl[u]);
            }
#pragma unroll
            for (int u = 0; u < 4; u++) {
                mma_bf16(c[2*u],   qh[kk], &kbh[u][0]);
                mma_bf16(c[2*u],   qh[kk], &kbl[u][0]);
                mma_bf16(c[2*u],   ql[kk], &kbh[u][0]);
                mma_bf16(c[2*u+1], qh[kk], &kbh[u][2]);
                mma_bf16(c[2*u+1], qh[kk], &kbl[u][2]);
                mma_bf16(c[2*u+1], ql[kk], &kbh[u][2]);
            }
        }
        const int rl0 = w*16 + (lane >> 2);
#pragma unroll
        for (int j = 0; j < 8; j++)
#pragma unroll
            for (int e = 0; e < 4; e++) c[j][e] *= 0.125f;
        if (kt == qt) {
#pragma unroll
            for (int j = 0; j < 8; j++) {
                int col = j*8 + 2*(lane & 3);
                if (col     > rl0)     c[j][0] = -1e30f;
                if (col + 1 > rl0)     c[j][1] = -1e30f;
                if (col     > rl0 + 8) c[j][2] = -1e30f;
                if (col + 1 > rl0 + 8) c[j][3] = -1e30f;
            }
        }
        float mx0 = -1e30f, mx1 = -1e30f;
#pragma unroll
        for (int j = 0; j < 8; j++) {
            mx0 = fmaxf(mx0, fmaxf(c[j][0], c[j][1]));
            mx1 = fmaxf(mx1, fmaxf(c[j][2], c[j][3]));
        }
        mx0 = fmaxf(mx0, __shfl_xor_sync(0xffffffffu, mx0, 1));
        mx0 = fmaxf(mx0, __shfl_xor_sync(0xffffffffu, mx0, 2));
        mx1 = fmaxf(mx1, __shfl_xor_sync(0xffffffffu, mx1, 1));
        mx1 = fmaxf(mx1, __shfl_xor_sync(0xffffffffu, mx1, 2));
        float mn0 = fmaxf(m0, mx0), mn1 = fmaxf(m1, mx1);
        float a0 = __expf(m0 - mn0), a1 = __expf(m1 - mn1);
        m0 = mn0; m1 = mn1;

        uint32_t ph[4][4], pl[4][4];
        float rs0 = 0.f, rs1 = 0.f;
#pragma unroll
        for (int t = 0; t < 4; t++) {
            float p00 = __expf(c[2*t][0]   - mn0), p01 = __expf(c[2*t][1]   - mn0);
            float p02 = __expf(c[2*t][2]   - mn1), p03 = __expf(c[2*t][3]   - mn1);
            float p10 = __expf(c[2*t+1][0] - mn0), p11 = __expf(c[2*t+1][1] - mn0);
            float p12 = __expf(c[2*t+1][2] - mn1), p13 = __expf(c[2*t+1][3] - mn1);
            rs0 += p00 + p01 + p10 + p11;
            rs1 += p02 + p03 + p12 + p13;
            float e0, e1;
            ph[t][0] = pack_hi2(p00, p01, e0, e1); pl[t][0] = packbf(e0, e1);
            ph[t][1] = pack_hi2(p02, p03, e0, e1); pl[t][1] = packbf(e0, e1);
            ph[t][2] = pack_hi2(p10, p11, e0, e1); pl[t][2] = packbf(e0, e1);
            ph[t][3] = pack_hi2(p12, p13, e0, e1); pl[t][3] = packbf(e0, e1);
        }
        rs0 += __shfl_xor_sync(0xffffffffu, rs0, 1);
        rs0 += __shfl_xor_sync(0xffffffffu, rs0, 2);
        rs1 += __shfl_xor_sync(0xffffffffu, rs1, 1);
        rs1 += __shfl_xor_sync(0xffffffffu, rs1, 2);
        l0 = l0*a0 + rs0;
        l1 = l1*a1 + rs1;
#pragma unroll
        for (int j = 0; j < 8; j++) {
            o[j][0] *= a0; o[j][1] *= a0;
            o[j][2] *= a1; o[j][3] *= a1;
        }
#pragma unroll
        for (int t = 0; t < 4; t++) {
#pragma unroll
            for (int u = 0; u < 4; u++) {
                int row = t*16 + (g8 & 1)*8 + rr8;
                int ch  = u*2 + (g8 >> 1);
                uint32_t off = (uint32_t)(row*8 + (ch ^ (row & 7)))*16;
                uint32_t vh_[4], vl_[4];
                ldsm_x4t(SV + off, vh_);
                ldsm_x4t(SV + 8192 + off, vl_);
                mma_bf16(o[2*u],   ph[t], &vh_[0]);
                mma_bf16(o[2*u],   pl[t], &vh_[0]);
                mma_bf16(o[2*u],   ph[t], &vl_[0]);
                mma_bf16(o[2*u+1], ph[t], &vh_[2]);
                mma_bf16(o[2*u+1], pl[t], &vh_[2]);
                mma_bf16(o[2*u+1], ph[t], &vl_[2]);
            }
        }
        __syncthreads();
    }

    float inv0 = 1.f / l0, inv1 = 1.f / l1;
    int rg0 = q0 + w*16 + (lane >> 2);
    float* base0 = s_att + (size_t)(b*Tt + rg0)*Cc + h*64;
    float* base1 = base0 + (size_t)8*Cc;
#pragma unroll
    for (int j = 0; j < 8; j++) {
        int colo = j*8 + 2*(lane & 3);
        *(float2*)(base0 + colo) = make_float2(o[j][0]*inv0, o[j][1]*inv0);
        *(float2*)(base1 + colo) = make_float2(o[j][2]*inv1, o[j][3]*inv1);
    }
}

// ---------------- launch ----------------
extern "C" void kernel_launch(void* const* d_in, const int* in_sizes, int n_in,
                              void* d_out, int out_size)
{
    (void)in_sizes; (void)n_in; (void)out_size;
    const float* x     = (const float*)d_in[0];
    const float* shift = (const float*)d_in[1];
    const float* maa_x = (const float*)d_in[2];
    const float* maa_r = (const float*)d_in[3];
    const float* maa_k = (const float*)d_in[4];
    const float* maa_v = (const float*)d_in[5];
    const float* w1    = (const float*)d_in[6];
    const float* w2    = (const float*)d_in[7];
    const float* Wq    = (const float*)d_in[8];
    const float* Wk    = (const float*)d_in[9];
    const float* Wv    = (const float*)d_in[10];
    const float* Wo    = (const float*)d_in[11];
    const float* g_r   = (const float*)d_in[12];
    const float* b_r   = (const float*)d_in[13];
    const float* g_k   = (const float*)d_in[14];
    const float* b_k   = (const float*)d_in[15];
    const float* g_v   = (const float*)d_in[16];
    const float* b_v   = (const float*)d_in[17];
    const float* g_x   = (const float*)d_in[18];
    const float* b_x   = (const float*)d_in[19];
    const float* cosT  = (const float*)d_in[20];
    const float* sinT  = (const float*)d_in[21];
    float* out = (float*)d_out;

    cudaFuncSetAttribute(k_gemm_qkv, cudaFuncAttributeMaxDynamicSharedMemorySize,
                         GEMM_SMEM_BYTES);
    cudaFuncSetAttribute(k_gemm_o, cudaFuncAttributeMaxDynamicSharedMemorySize,
                         GEMM_SMEM_BYTES);
    cudaFuncSetAttribute(k_attn_tc, cudaFuncAttributeMaxDynamicSharedMemorySize,
                         ATTN_SMEM_BYTES);

    k_wcvt<<<dim3(Cc*Cc/1024, 4), 256>>>(Wq, Wk, Wv, Wo);
    k_lora1<<<NT/16, 96>>>(x, shift, maa_x, w1);
    k_mix<<<dim3(Cc/64, NT/16), 256>>>(x, shift, w2, maa_r, maa_k, maa_v);
    k_gemm_qkv<<<dim3(Cc/64, 16, 3), 256, GEMM_SMEM_BYTES>>>();
    k_lnqkv<<<dim3(NT, 3), 256>>>(g_r, b_r, g_k, b_k, g_v, b_v, cosT, sinT);
    k_attn_tc<<<dim3(16, Bb*Hh), 128, ATTN_SMEM_BYTES>>>();
    k_lnplain<<<NT, 256>>>(g_x, b_x);
    k_gemm_o<<<dim3(Cc/64, 16), 256, GEMM_SMEM_BYTES>>>(out);
}

// round 14
// speedup vs baseline: 1.0323x; 1.0306x over previous
#include <cuda_runtime.h>
#include <cuda_bf16.h>
#include <math.h>
#include <stdint.h>

#define Bb 2
#define Tt 1024
#define Cc 2048
#define Hh 32
#define Dd 64
#define NT (Bb*Tt)
#define L3 96

// ---------------- scratch ----------------
__device__ __align__(16) float s_h [NT*L3];
__device__ __align__(16) float s_yq[NT*Cc];
__device__ __align__(16) float s_yk[NT*Cc];
__device__ __align__(16) float s_yv[NT*Cc];
__device__ __align__(16) float s_att[NT*Cc];

// bf16 hi/lo planes
__device__ __align__(16) __nv_bfloat16 a_hi[3][NT*Cc];
__device__ __align__(16) __nv_bfloat16 a_lo[3][NT*Cc];
__device__ __align__(16) __nv_bfloat16 o_hi[NT*Cc];
__device__ __align__(16) __nv_bfloat16 o_lo[NT*Cc];
__device__ __align__(16) __nv_bfloat16 w_hi[4][Cc*Cc];
__device__ __align__(16) __nv_bfloat16 w_lo[4][Cc*Cc];
// head-layout q/k/v planes [B*H][T][64]
__device__ __align__(16) __nv_bfloat16 qp_hi[NT*Cc];
__device__ __align__(16) __nv_bfloat16 qp_lo[NT*Cc];
__device__ __align__(16) __nv_bfloat16 kp_hi[NT*Cc];
__device__ __align__(16) __nv_bfloat16 kp_lo[NT*Cc];
__device__ __align__(16) __nv_bfloat16 vp_hi[NT*Cc];
__device__ __align__(16) __nv_bfloat16 vp_lo[NT*Cc];

// ============ helpers ============
__device__ __forceinline__ uint32_t cvta_sm(const void* p) {
    return (uint32_t)__cvta_generic_to_shared(p);
}
__device__ __forceinline__ void ldsm_x4(uint32_t addr, uint32_t* r) {
    asm volatile("ldmatrix.sync.aligned.m8n8.x4.shared.b16 {%0,%1,%2,%3},[%4];"
        : "=r"(r[0]), "=r"(r[1]), "=r"(r[2]), "=r"(r[3]) : "r"(addr));
}
__device__ __forceinline__ void ldsm_x4t(uint32_t addr, uint32_t* r) {
    asm volatile("ldmatrix.sync.aligned.m8n8.x4.trans.shared.b16 {%0,%1,%2,%3},[%4];"
        : "=r"(r[0]), "=r"(r[1]), "=r"(r[2]), "=r"(r[3]) : "r"(addr));
}
__device__ __forceinline__ void mma_bf16(float* d, const uint32_t* a, const uint32_t* b) {
    asm volatile(
        "mma.sync.aligned.m16n8k16.row.col.f32.bf16.bf16.f32 "
        "{%0,%1,%2,%3},{%4,%5,%6,%7},{%8,%9},{%0,%1,%2,%3};"
        : "+f"(d[0]), "+f"(d[1]), "+f"(d[2]), "+f"(d[3])
        : "r"(a[0]), "r"(a[1]), "r"(a[2]), "r"(a[3]), "r"(b[0]), "r"(b[1]));
}
__device__ __forceinline__ uint32_t packbf(float x, float y) {
    __nv_bfloat162 h = __floats2bfloat162_rn(x, y);
    return *(uint32_t*)&h;
}
__device__ __forceinline__ uint32_t pack_hi2(float x, float y, float& rx, float& ry) {
    __nv_bfloat16 hx = __float2bfloat16_rn(x), hy = __float2bfloat16_rn(y);
    rx = x - __bfloat162float(hx);
    ry = y - __bfloat162float(hy);
    return ((uint32_t)*(uint16_t*)&hy << 16) | *(uint16_t*)&hx;
}
__device__ __forceinline__ void cp16(uint32_t dst, const void* src) {
    asm volatile("cp.async.cg.shared.global [%0], [%1], 16;" :: "r"(dst), "l"(src));
}
__device__ __forceinline__ void cp_commit() {
    asm volatile("cp.async.commit_group;" ::: "memory");
}
template<int N> __device__ __forceinline__ void cp_wait() {
    asm volatile("cp.async.wait_group %0;" :: "n"(N) : "memory");
}

// ---------------- weight pre-split ----------------
__global__ __launch_bounds__(256) void k_wcvt(
    const float* __restrict__ Wq, const float* __restrict__ Wk,
    const float* __restrict__ Wv, const float* __restrict__ Wo)
{
    int m = blockIdx.y;
    const float* src = (m == 0) ? Wq : (m == 1) ? Wk : (m == 2) ? Wv : Wo;
    size_t e = ((size_t)blockIdx.x * 256 + threadIdx.x) * 4;
    float4 v = *(const float4*)(src + e);
    float r0,r1,r2,r3;
    uint2 hi, lo;
    hi.x = pack_hi2(v.x, v.y, r0, r1);
    hi.y = pack_hi2(v.z, v.w, r2, r3);
    lo.x = packbf(r0, r1);
    lo.y = packbf(r2, r3);
    *(uint2*)&w_hi[m][e] = hi;
    *(uint2*)&w_lo[m][e] = lo;
}

// ---------------- LoRA stage 1 (xx inline; 192 thr, 8 rows/CTA) ----------
__global__ __launch_bounds__(192) void k_lora1(
    const float* __restrict__ x, const float* __restrict__ shift,
    const float* __restrict__ maa_x, const float* __restrict__ w1)
{
    __shared__ float xs[8][128];
    int n0 = blockIdx.x * 8;
    int j    = threadIdx.x % 96;
    int half = threadIdx.x / 96;          // 0..1 -> rows half*4 .. half*4+3
    float acc[4];
#pragma unroll
    for (int r = 0; r < 4; r++) acc[r] = 0.f;
    for (int k0 = 0; k0 < Cc; k0 += 128) {
        __syncthreads();
        for (int i = threadIdx.x; i < 8*128; i += 192) {
            int r = i >> 7, cc = i & 127;
            int row = n0 + r, c = k0 + cc;
            int t = row & (Tt - 1), b = row >> 10;
            float xv = x[(size_t)row*Cc + c];
            float xp = (t == 0) ? shift[b*Cc + c] : x[(size_t)(row-1)*Cc + c];
            xs[r][cc] = fmaf(xp - xv, maa_x[c], xv);
        }
        __syncthreads();
        for (int k = 0; k < 128; k++) {
            float wv = w1[(k0 + k)*L3 + j];
#pragma unroll
            for (int r = 0; r < 4; r++)
                acc[r] = fmaf(xs[half*4 + r][k], wv, acc[r]);
        }
    }
#pragma unroll
    for (int r = 0; r < 4; r++)
        s_h[(n0 + half*4 + r)*L3 + j] = tanhf(acc[r]);
}

// ---------------- LoRA stage 2 + mixing ----------
__global__ __launch_bounds__(256) void k_mix(
    const float* __restrict__ x, const float* __restrict__ shift,
    const float* __restrict__ w2,
    const float* __restrict__ maa_r, const float* __restrict__ maa_k,
    const float* __restrict__ maa_v)
{
    __shared__ float w2s[96][64];
    __shared__ float hs[16][96];
    int c0 = blockIdx.x * 64;
    int n0 = blockIdx.y * 16;
    int tid = threadIdx.x;
    for (int i = tid; i < 96*64; i += 256) {
        int rr = i >> 6, cc = i & 63;
        w2s[rr][cc] = w2[rr*Cc + c0 + cc];
    }
    for (int i = tid; i < 16*96; i += 256) {
        int rr = i / 96, jj = i % 96;
        hs[rr][jj] = s_h[(n0 + rr)*L3 + jj];
    }
    __syncthreads();
    int col = tid & 63, rg = tid >> 6;
    int c = c0 + col;
    float ar = maa_r[c], ak = maa_k[c], av = maa_v[c];
#pragma unroll
    for (int rr = 0; rr < 4; rr++) {
        int r = rg*4 + rr;
        float m0 = 0.f, m1 = 0.f, m2 = 0.f;
#pragma unroll
        for (int i = 0; i < 32; i++) {
            m0 = fmaf(hs[r][i],      w2s[i][col],      m0);
            m1 = fmaf(hs[r][32 + i], w2s[32 + i][col], m1);
            m2 = fmaf(hs[r][64 + i], w2s[64 + i][col], m2);
        }
        int row = n0 + r;
        int t = row & (Tt - 1), b = row >> 10;
        size_t idx = (size_t)row*Cc + c;
        float xf = x[idx];
        float xp = (t == 0) ? shift[b*Cc + c] : x[idx - Cc];
        float dxf = xp - xf;
        float vr = fmaf(dxf, ar + m0, xf);
        float vk = fmaf(dxf, ak + m1, xf);
        float vv = fmaf(dxf, av + m2, xf);
        __nv_bfloat16 hr = __float2bfloat16_rn(vr);
        __nv_bfloat16 hk = __float2bfloat16_rn(vk);
        __nv_bfloat16 hv = __float2bfloat16_rn(vv);
        a_hi[0][idx] = hr; a_lo[0][idx] = __float2bfloat16_rn(vr - __bfloat162float(hr));
        a_hi[1][idx] = hk; a_lo[1][idx] = __float2bfloat16_rn(vk - __bfloat162float(hk));
        a_hi[2][idx] = hv; a_lo[2][idx] = __float2bfloat16_rn(vv - __bfloat162float(hv));
    }
}

// ============ bf16 3-term GEMM, CTA tile 128x64, 3-stage cp.async ============
#define GEMM_SMEM_BYTES 73728

__device__ __forceinline__ void gemm_cp(
    const __nv_bfloat16* __restrict__ Ah, const __nv_bfloat16* __restrict__ Al,
    const __nv_bfloat16* __restrict__ Bh, const __nv_bfloat16* __restrict__ Bl,
    float* __restrict__ Cm)
{
    extern __shared__ __align__(16) unsigned char smema[];
    const uint32_t sm0 = cvta_sm(smema);
    const int tid = threadIdx.x, lane = tid & 31, wid = tid >> 5;
    const int wm = wid >> 1, wn = wid & 1;
    const int m0 = blockIdx.y * 128, n0 = blockIdx.x * 64;

    auto issue = [&](int kt, int s) {
        uint32_t SS = sm0 + s*24576;
#pragma unroll
        for (int t = 0; t < 4; t++) {
            int idx = tid + t*256;
            int term = idx >> 9, ksub = (idx >> 8) & 1;
            int row = (idx >> 1) & 127, ch = idx & 1;
            const __nv_bfloat16* src = (term ? Al : Ah)
                + (size_t)(m0 + row)*Cc + kt*32 + ksub*16 + ch*8;
            uint32_t dst = SS + term*8192 + ksub*4096 + row*32
                         + ((ch ^ ((row >> 2) & 1))*16);
            cp16(dst, src);
        }
#pragma unroll
        for (int t = 0; t < 2; t++) {
            int idx = tid + t*256;
            int term = idx >> 8, kr = (idx >> 3) & 31, ch = idx & 7;
            const __nv_bfloat16* src = (term ? Bl : Bh)
                + (size_t)(kt*32 + kr)*Cc + n0 + ch*8;
            uint32_t dst = SS + 16384 + term*4096 + kr*128 + ((ch ^ (kr & 7))*16);
            cp16(dst, src);
        }
        cp_commit();
    };

    float acc[2][4][4];
#pragma unroll
    for (int i = 0; i < 2; i++)
#pragma unroll
        for (int j = 0; j < 4; j++)
#pragma unroll
            for (int e = 0; e < 4; e++) acc[i][j][e] = 0.f;

    const int rlA = lane & 15;
    const int selA = lane >> 4;
    const int krB = ((lane >> 3) & 1)*8 + (lane & 7);
    const int ncB = lane >> 4;

    issue(0, 0);
    issue(1, 1);
    const int NKT = Cc / 32;
    for (int kt = 0; kt < NKT; kt++) {
        if (kt + 1 < NKT) cp_wait<1>(); else cp_wait<0>();
        __syncthreads();
        if (kt + 2 < NKT) issue(kt + 2, (kt + 2) % 3);
        uint32_t SS = sm0 + (kt % 3)*24576;
#pragma unroll
        for (int ksub = 0; ksub < 2; ksub++) {
            uint32_t Ahf[2][4], Alf[2][4], Bhf[4][2], Blf[4][2];
#pragma unroll
            for (int i = 0; i < 2; i++) {
                int row = wm*32 + i*16 + rlA;
                uint32_t off = SS + ksub*4096 + row*32
                             + ((selA ^ ((row >> 2) & 1))*16);
                ldsm_x4(off, Ahf[i]);
                ldsm_x4(off + 8192, Alf[i]);
            }
#pragma unroll
            for (int jj = 0; jj < 2; jj++) {
                int kr = ksub*16 + krB;
                int nchunk = wn*4 + jj*2 + ncB;
                uint32_t off = SS + 16384 + kr*128 + ((nchunk ^ (kr & 7))*16);
                uint32_t tmp[4];
                ldsm_x4t(off, tmp);
                Bhf[2*jj][0] = tmp[0]; Bhf[2*jj][1] = tmp[1];
                Bhf[2*jj+1][0] = tmp[2]; Bhf[2*jj+1][1] = tmp[3];
                ldsm_x4t(off + 4096, tmp);
                Blf[2*jj][0] = tmp[0]; Blf[2*jj][1] = tmp[1];
                Blf[2*jj+1][0] = tmp[2]; Blf[2*jj+1][1] = tmp[3];
            }
            // three passes: 8 independent accumulators between same-acc reuse
#pragma unroll
            for (int i = 0; i < 2; i++)
#pragma unroll
                for (int j = 0; j < 4; j++)
                    mma_bf16(acc[i][j], Ahf[i], Bhf[j]);
#pragma unroll
            for (int i = 0; i < 2; i++)
#pragma unroll
                for (int j = 0; j < 4; j++)
                    mma_bf16(acc[i][j], Ahf[i], Blf[j]);
#pragma unroll
            for (int i = 0; i < 2; i++)
#pragma unroll
                for (int j = 0; j < 4; j++)
                    mma_bf16(acc[i][j], Alf[i], Bhf[j]);
        }
    }

    const int g = lane >> 2, tq = lane & 3;
#pragma unroll
    for (int i = 0; i < 2; i++) {
#pragma unroll
        for (int j = 0; j < 4; j++) {
            int row = m0 + wm*32 + i*16 + g;
            int col = n0 + wn*32 + j*8 + tq*2;
            *(float2*)(Cm + (size_t)row*Cc + col) =
                make_float2(acc[i][j][0], acc[i][j][1]);
            *(float2*)(Cm + (size_t)(row + 8)*Cc + col) =
                make_float2(acc[i][j][2], acc[i][j][3]);
        }
    }
}

__global__ __launch_bounds__(256, 2) void k_gemm_qkv()
{
    int z = blockIdx.z;
    float* C = (z == 0) ? s_yq : (z == 1) ? s_yk : s_yv;
    gemm_cp(a_hi[z], a_lo[z], w_hi[z], w_lo[z], C);
}

__global__ __launch_bounds__(256, 2) void k_gemm_o(float* __restrict__ out)
{
    gemm_cp(o_hi, o_lo, w_hi[3], w_lo[3], out);
}

// ---------------- LN (+RoPE) into head-layout bf16 hi/lo planes -------------
__global__ __launch_bounds__(256) void k_lnqkv(
    const float* __restrict__ gr, const float* __restrict__ br_,
    const float* __restrict__ gk, const float* __restrict__ bk_,
    const float* __restrict__ gv, const float* __restrict__ bv_,
    const float* __restrict__ cosT, const float* __restrict__ sinT)
{
    int mode = blockIdx.y;
    const float* Y; const float* g; const float* bbv;
    __nv_bfloat16 *phi, *plo;
    if (mode == 0)      { Y = s_yq; g = gr; bbv = br_; phi = qp_hi; plo = qp_lo; }
    else if (mode == 1) { Y = s_yk; g = gk; bbv = bk_; phi = kp_hi; plo = kp_lo; }
    else                { Y = s_yv; g = gv; bbv = bv_; phi = vp_hi; plo = vp_lo; }
    int row = blockIdx.x;
    int t = row & (Tt - 1), b = row >> 10;
    __shared__ float srow[Cc];
    __shared__ float red[64];
    const float* yr = Y + (size_t)row*Cc;
    float sum = 0.f, sq = 0.f, vals[8];
#pragma unroll
    for (int k = 0; k < 8; k++) {
        float v = yr[threadIdx.x + k*256];
        vals[k] = v; sum += v; sq = fmaf(v, v, sq);
    }
#pragma unroll
    for (int o = 16; o; o >>= 1) {
        sum += __shfl_xor_sync(0xffffffffu, sum, o);
        sq  += __shfl_xor_sync(0xffffffffu, sq,  o);
    }
    int w = threadIdx.x >> 5;
    if ((threadIdx.x & 31) == 0) { red[w] = sum; red[32 + w] = sq; }
    __syncthreads();
    if (threadIdx.x < 32) {
        float s1 = (threadIdx.x < 8) ? red[threadIdx.x] : 0.f;
        float s2 = (threadIdx.x < 8) ? red[32 + threadIdx.x] : 0.f;
#pragma unroll
        for (int o = 4; o; o >>= 1) {
            s1 += __shfl_xor_sync(0xffffffffu, s1, o);
            s2 += __shfl_xor_sync(0xffffffffu, s2, o);
        }
        if (threadIdx.x == 0) { red[0] = s1; red[32] = s2; }
    }
    __syncthreads();
    float mu  = red[0]  * (1.f/Cc);
    float var = red[32] * (1.f/Cc) - mu*mu;
    float inv = rsqrtf(var + 1e-5f);
#pragma unroll
    for (int k = 0; k < 8; k++) {
        int c = threadIdx.x + k*256;
        srow[c] = (vals[k] - mu)*inv*g[c] + bbv[c];
    }
    __syncthreads();
#pragma unroll
    for (int k = 0; k < 8; k++) {
        int c = threadIdx.x + k*256;
        int h = c >> 6, d = c & 63;
        float o;
        if (mode == 2) { o = srow[c]; }
        else if (d < 32) {
            float cc = cosT[t*32 + d], ss = sinT[t*32 + d];
            o = srow[c]*cc - srow[c + 32]*ss;
        } else {
            int d2 = d - 32;
            float cc = cosT[t*32 + d2], ss = sinT[t*32 + d2];
            o = srow[c - 32]*ss + srow[c]*cc;
        }
        size_t off = (((size_t)(b*Hh + h)*Tt + t) << 6) + d;
        __nv_bfloat16 hv = __float2bfloat16_rn(o);
        phi[off] = hv;
        plo[off] = __float2bfloat16_rn(o - __bfloat162float(hv));
    }
}

// ---------------- LN of attention output (writes bf16 hi/lo) -------------
__global__ __launch_bounds__(256) void k_lnplain(
    const float* __restrict__ gx, const float* __restrict__ bx)
{
    int row = blockIdx.x;
    __shared__ float red[64];
    const float* yr = s_att + (size_t)row*Cc;
    float sum = 0.f, sq = 0.f, vals[8];
#pragma unroll
    for (int k = 0; k < 8; k++) {
        float v = yr[threadIdx.x + k*256];
        vals[k] = v; sum += v; sq = fmaf(v, v, sq);
    }
#pragma unroll
    for (int o = 16; o; o >>= 1) {
        sum += __shfl_xor_sync(0xffffffffu, sum, o);
        sq  += __shfl_xor_sync(0xffffffffu, sq,  o);
    }
    int w = threadIdx.x >> 5;
    if ((threadIdx.x & 31) == 0) { red[w] = sum; red[32 + w] = sq; }
    __syncthreads();
    if (threadIdx.x < 32) {
        float s1 = (threadIdx.x < 8) ? red[threadIdx.x] : 0.f;
        float s2 = (threadIdx.x < 8) ? red[32 + threadIdx.x] : 0.f;
#pragma unroll
        for (int o = 4; o; o >>= 1) {
            s1 += __shfl_xor_sync(0xffffffffu, s1, o);
            s2 += __shfl_xor_sync(0xffffffffu, s2, o);
        }
        if (threadIdx.x == 0) { red[0] = s1; red[32] = s2; }
    }
    __syncthreads();
    float mu  = red[0]  * (1.f/Cc);
    float var = red[32] * (1.f/Cc) - mu*mu;
    float inv = rsqrtf(var + 1e-5f);
    size_t rb = (size_t)row*Cc;
#pragma unroll
    for (int k = 0; k < 8; k++) {
        int c = threadIdx.x + k*256;
        float v = (vals[k] - mu)*inv*gx[c] + bx[c];
        __nv_bfloat16 hv = __float2bfloat16_rn(v);
        o_hi[rb + c] = hv;
        o_lo[rb + c] = __float2bfloat16_rn(v - __bfloat162float(hv));
    }
}

// ======== causal flash attention: cp.async pre-split tiles, 3x-bf16 ========
#define ATTN_SMEM_BYTES 81920

__global__ __launch_bounds__(128, 2) void k_attn_tc()
{
    extern __shared__ __align__(16) unsigned char asmem[];
    const uint32_t sb = cvta_sm(asmem);

    const int qt  = (int)gridDim.x - 1 - (int)blockIdx.x;
    const int bh  = blockIdx.y;
    const int b   = bh >> 5, h = bh & 31;
    const int tid = threadIdx.x, lane = tid & 31, w = tid >> 5;
    const int q0  = qt * 64;
    const size_t basebh = (size_t)bh*Tt*64;

    auto issueKV = [&](int kt2, int s) {
        uint32_t SS = sb + 16384 + s*32768;
        int s0 = kt2*64;
#pragma unroll
        for (int i = 0; i < 4; i++) {
            int idx = tid + i*128;
            int row = idx >> 3, ch = idx & 7;
            uint32_t o = (uint32_t)((row*8 + (ch ^ (row & 7)))*16);
            size_t src = basebh + (size_t)(s0 + row)*64 + ch*8;
            cp16(SS + o,         kp_hi + src);
            cp16(SS + 8192 + o,  kp_lo + src);
            cp16(SS + 16384 + o, vp_hi + src);
            cp16(SS + 24576 + o, vp_lo + src);
        }
        cp_commit();
    };

    {
#pragma unroll
        for (int i = 0; i < 4; i++) {
            int idx = tid + i*128;
            int row = idx >> 3, ch = idx & 7;
            uint32_t o = (uint32_t)((row*8 + (ch ^ (row & 7)))*16);
            size_t src = basebh + (size_t)(q0 + row)*64 + ch*8;
            cp16(sb + o,        qp_hi + src);
            cp16(sb + 8192 + o, qp_lo + src);
        }
        cp_commit();
    }
    issueKV(0, 0);
    cp_wait<1>();
    __syncthreads();

    uint32_t qh[4][4], ql[4][4];
    const int g8 = lane >> 3, rr8 = lane & 7;
#pragma unroll
    for (int kk = 0; kk < 4; kk++) {
        int row = w*16 + (g8 & 1)*8 + rr8;
        int ch  = kk*2 + (g8 >> 1);
        uint32_t off = (uint32_t)(row*8 + (ch ^ (row & 7)))*16;
        ldsm_x4(sb + off, qh[kk]);
        ldsm_x4(sb + 8192 + off, ql[kk]);
    }

    float o[8][4];
#pragma unroll
    for (int j = 0; j < 8; j++)
#pragma unroll
        for (int e = 0; e < 4; e++) o[j][e] = 0.f;
    float m0 = -1e30f, m1 = -1e30f, l0 = 0.f, l1 = 0.f;

    for (int kt = 0; kt <= qt; kt++) {
        if (kt + 1 <= qt) { issueKV(kt + 1, (kt + 1) & 1); cp_wait<1>(); }
        else              { cp_wait<0>(); }
        __syncthreads();
        const uint32_t SK = sb + 16384 + (kt & 1)*32768;
        const uint32_t SV = SK + 16384;

        float c[8][4];
#pragma unroll
        for (int j = 0; j < 8; j++)
#pragma unroll
            for (int e = 0; e < 4; e++) c[j][e] = 0.f;
#pragma unroll
        for (int kk = 0; kk < 4; kk++) {
            uint32_t kbh[4][4], kbl[4][4];
#pragma unroll
            for (int u = 0; u < 4; u++) {
                int row = u*16 + (g8 >> 1)*8 + rr8;
                int ch  = kk*2 + (g8 & 1);
                uint32_t off = (uint32_t)(row*8 + (ch ^ (row & 7)))*16;
                ldsm_x4(SK + off, kbh[u]);
                ldsm_x4(SK + 8192 + off, kbl[u]);
            }
            // three passes over 8 independent accumulators
#pragma unroll
            for (int u = 0; u < 4; u++) {
                mma_bf16(c[2*u],   qh[kk], &kbh[u][0]);
                mma_bf16(c[2*u+1], qh[kk], &kbh[u][2]);
            }
#pragma unroll
            for (int u = 0; u < 4; u++) {
                mma_bf16(c[2*u],   qh[kk], &kbl[u][0]);
                mma_bf16(c[2*u+1], qh[kk], &kbl[u][2]);
            }
#pragma unroll
            for (int u = 0; u < 4; u++) {
                mma_bf16(c[2*u],   ql[kk], &kbh[u][0]);
                mma_bf16(c[2*u+1], ql[kk], &kbh[u][2]);
            }
        }
        const int rl0 = w*16 + (lane >> 2);
#pragma unroll
        for (int j = 0; j < 8; j++)
#pragma unroll
            for (int e = 0; e < 4; e++) c[j][e] *= 0.125f;
        if (kt == qt) {
#pragma unroll
            for (int j = 0; j < 8; j++) {
                int col = j*8 + 2*(lane & 3);
                if (col     > rl0)     c[j][0] = -1e30f;
                if (col + 1 > rl0)     c[j][1] = -1e30f;
                if (col     > rl0 + 8) c[j][2] = -1e30f;
                if (col + 1 > rl0 + 8) c[j][3] = -1e30f;
            }
        }
        float mx0 = -1e30f, mx1 = -1e30f;
#pragma unroll
        for (int j = 0; j < 8; j++) {
            mx0 = fmaxf(mx0, fmaxf(c[j][0], c[j][1]));
            mx1 = fmaxf(mx1, fmaxf(c[j][2], c[j][3]));
        }
        mx0 = fmaxf(mx0, __shfl_xor_sync(0xffffffffu, mx0, 1));
        mx0 = fmaxf(mx0, __shfl_xor_sync(0xffffffffu, mx0, 2));
        mx1 = fmaxf(mx1, __shfl_xor_sync(0xffffffffu, mx1, 1));
        mx1 = fmaxf(mx1, __shfl_xor_sync(0xffffffffu, mx1, 2));
        float mn0 = fmaxf(m0, mx0), mn1 = fmaxf(m1, mx1);
        float a0 = __expf(m0 - mn0), a1 = __expf(m1 - mn1);
        m0 = mn0; m1 = mn1;

        uint32_t ph[4][4], pl[4][4];
        float rs0 = 0.f, rs1 = 0.f;
#pragma unroll
        for (int t = 0; t < 4; t++) {
            float p00 = __expf(c[2*t][0]   - mn0), p01 = __expf(c[2*t][1]   - mn0);
            float p02 = __expf(c[2*t][2]   - mn1), p03 = __expf(c[2*t][3]   - mn1);
            float p10 = __expf(c[2*t+1][0] - mn0), p11 = __expf(c[2*t+1][1] - mn0);
            float p12 = __expf(c[2*t+1][2] - mn1), p13 = __expf(c[2*t+1][3] - mn1);
            rs0 += p00 + p01 + p10 + p11;
            rs1 += p02 + p03 + p12 + p13;
            float e0, e1;
            ph[t][0] = pack_hi2(p00, p01, e0, e1); pl[t][0] = packbf(e0, e1);
            ph[t][1] = pack_hi2(p02, p03, e0, e1); pl[t][1] = packbf(e0, e1);
            ph[t][2] = pack_hi2(p10, p11, e0, e1); pl[t][2] = packbf(e0, e1);
            ph[t][3] = pack_hi2(p12, p13, e0, e1); pl[t][3] = packbf(e0, e1);
        }
        rs0 += __shfl_xor_sync(0xffffffffu, rs0, 1);
        rs0 += __shfl_xor_sync(0xffffffffu, rs0, 2);
        rs1 += __shfl_xor_sync(0xffffffffu, rs1, 1);
        rs1 += __shfl_xor_sync(0xffffffffu, rs1, 2);
        l0 = l0*a0 + rs0;
        l1 = l1*a1 + rs1;
#pragma unroll
        for (int j = 0; j < 8; j++) {
            o[j][0] *= a0; o[j][1] *= a0;
            o[j][2] *= a1; o[j][3] *= a1;
        }
#pragma unroll
        for (int t = 0; t < 4; t++) {
#pragma unroll
            for (int u = 0; u < 4; u++) {
                int row = t*16 + (g8 & 1)*8 + rr8;
                int ch  = u*2 + (g8 >> 1);
                uint32_t off = (uint32_t)(row*8 + (ch ^ (row & 7)))*16;
                uint32_t vh_[4], vl_[4];
                ldsm_x4t(SV + off, vh_);
                ldsm_x4t(SV + 8192 + off, vl_);
                // interleave the two accumulators (distance-2 same-acc)
                mma_bf16(o[2*u],   ph[t], &vh_[0]);
                mma_bf16(o[2*u+1], ph[t], &vh_[2]);
                mma_bf16(o[2*u],   pl[t], &vh_[0]);
                mma_bf16(o[2*u+1], pl[t], &vh_[2]);
                mma_bf16(o[2*u],   ph[t], &vl_[0]);
                mma_bf16(o[2*u+1], ph[t], &vl_[2]);
            }
        }
        __syncthreads();
    }

    float inv0 = 1.f / l0, inv1 = 1.f / l1;
    int rg0 = q0 + w*16 + (lane >> 2);
    float* base0 = s_att + (size_t)(b*Tt + rg0)*Cc + h*64;
    float* base1 = base0 + (size_t)8*Cc;
#pragma unroll
    for (int j = 0; j < 8; j++) {
        int colo = j*8 + 2*(lane & 3);
        *(float2*)(base0 + colo) = make_float2(o[j][0]*inv0, o[j][1]*inv0);
        *(float2*)(base1 + colo) = make_float2(o[j][2]*inv1, o[j][3]*inv1);
    }
}

// ---------------- launch ----------------
extern "C" void kernel_launch(void* const* d_in, const int* in_sizes, int n_in,
                              void* d_out, int out_size)
{
    (void)in_sizes; (void)n_in; (void)out_size;
    const float* x     = (const float*)d_in[0];
    const float* shift = (const float*)d_in[1];
    const float* maa_x = (const float*)d_in[2];
    const float* maa_r = (const float*)d_in[3];
    const float* maa_k = (const float*)d_in[4];
    const float* maa_v = (const float*)d_in[5];
    const float* w1    = (const float*)d_in[6];
    const float* w2    = (const float*)d_in[7];
    const float* Wq    = (const float*)d_in[8];
    const float* Wk    = (const float*)d_in[9];
    const float* Wv    = (const float*)d_in[10];
    const float* Wo    = (const float*)d_in[11];
    const float* g_r   = (const float*)d_in[12];
    const float* b_r   = (const float*)d_in[13];
    const float* g_k   = (const float*)d_in[14];
    const float* b_k   = (const float*)d_in[15];
    const float* g_v   = (const float*)d_in[16];
    const float* b_v   = (const float*)d_in[17];
    const float* g_x   = (const float*)d_in[18];
    const float* b_x   = (const float*)d_in[19];
    const float* cosT  = (const float*)d_in[20];
    const float* sinT  = (const float*)d_in[21];
    float* out = (float*)d_out;

    cudaFuncSetAttribute(k_gemm_qkv, cudaFuncAttributeMaxDynamicSharedMemorySize,
                         GEMM_SMEM_BYTES);
    cudaFuncSetAttribute(k_gemm_o, cudaFuncAttributeMaxDynamicSharedMemorySize,
                         GEMM_SMEM_BYTES);
    cudaFuncSetAttribute(k_attn_tc, cudaFuncAttributeMaxDynamicSharedMemorySize,
                         ATTN_SMEM_BYTES);

    k_wcvt<<<dim3(Cc*Cc/1024, 4), 256>>>(Wq, Wk, Wv, Wo);
    k_lora1<<<NT/8, 192>>>(x, shift, maa_x, w1);
    k_mix<<<dim3(Cc/64, NT/16), 256>>>(x, shift, w2, maa_r, maa_k, maa_v);
    k_gemm_qkv<<<dim3(Cc/64, 16, 3), 256, GEMM_SMEM_BYTES>>>();
    k_lnqkv<<<dim3(NT, 3), 256>>>(g_r, b_r, g_k, b_k, g_v, b_v, cosT, sinT);
    k_attn_tc<<<dim3(16, Bb*Hh), 128, ATTN_SMEM_BYTES>>>();
    k_lnplain<<<NT, 256>>>(g_x, b_x);
    k_gemm_o<<<dim3(Cc/64, 16), 256, GEMM_SMEM_BYTES>>>(out);
}

// round 15
// speedup vs baseline: 1.1103x; 1.0756x over previous
#include <cuda_runtime.h>
#include <cuda_bf16.h>
#include <math.h>
#include <stdint.h>

#define Bb 2
#define Tt 1024
#define Cc 2048
#define Hh 32
#define Dd 64
#define NT (Bb*Tt)
#define L3 96

// ---------------- scratch ----------------
__device__ __align__(16) float s_h [NT*L3];
__device__ __align__(16) float s_yq[NT*Cc];
__device__ __align__(16) float s_yk[NT*Cc];
__device__ __align__(16) float s_yv[NT*Cc];
__device__ __align__(16) float s_att[NT*Cc];

// bf16 hi/lo planes
__device__ __align__(16) __nv_bfloat16 a_hi[3][NT*Cc];
__device__ __align__(16) __nv_bfloat16 a_lo[3][NT*Cc];
__device__ __align__(16) __nv_bfloat16 o_hi[NT*Cc];
__device__ __align__(16) __nv_bfloat16 o_lo[NT*Cc];
__device__ __align__(16) __nv_bfloat16 w_hi[4][Cc*Cc];
__device__ __align__(16) __nv_bfloat16 w_lo[4][Cc*Cc];
// head-layout q/k/v planes [B*H][T][64]
__device__ __align__(16) __nv_bfloat16 qp_hi[NT*Cc];
__device__ __align__(16) __nv_bfloat16 qp_lo[NT*Cc];
__device__ __align__(16) __nv_bfloat16 kp_hi[NT*Cc];
__device__ __align__(16) __nv_bfloat16 kp_lo[NT*Cc];
__device__ __align__(16) __nv_bfloat16 vp_hi[NT*Cc];
__device__ __align__(16) __nv_bfloat16 vp_lo[NT*Cc];

// ============ helpers ============
__device__ __forceinline__ uint32_t cvta_sm(const void* p) {
    return (uint32_t)__cvta_generic_to_shared(p);
}
__device__ __forceinline__ void ldsm_x4(uint32_t addr, uint32_t* r) {
    asm volatile("ldmatrix.sync.aligned.m8n8.x4.shared.b16 {%0,%1,%2,%3},[%4];"
        : "=r"(r[0]), "=r"(r[1]), "=r"(r[2]), "=r"(r[3]) : "r"(addr));
}
__device__ __forceinline__ void ldsm_x4t(uint32_t addr, uint32_t* r) {
    asm volatile("ldmatrix.sync.aligned.m8n8.x4.trans.shared.b16 {%0,%1,%2,%3},[%4];"
        : "=r"(r[0]), "=r"(r[1]), "=r"(r[2]), "=r"(r[3]) : "r"(addr));
}
__device__ __forceinline__ void mma_bf16(float* d, const uint32_t* a, const uint32_t* b) {
    asm volatile(
        "mma.sync.aligned.m16n8k16.row.col.f32.bf16.bf16.f32 "
        "{%0,%1,%2,%3},{%4,%5,%6,%7},{%8,%9},{%0,%1,%2,%3};"
        : "+f"(d[0]), "+f"(d[1]), "+f"(d[2]), "+f"(d[3])
        : "r"(a[0]), "r"(a[1]), "r"(a[2]), "r"(a[3]), "r"(b[0]), "r"(b[1]));
}
__device__ __forceinline__ uint32_t packbf(float x, float y) {
    __nv_bfloat162 h = __floats2bfloat162_rn(x, y);
    return *(uint32_t*)&h;
}
__device__ __forceinline__ uint32_t pack_hi2(float x, float y, float& rx, float& ry) {
    __nv_bfloat16 hx = __float2bfloat16_rn(x), hy = __float2bfloat16_rn(y);
    rx = x - __bfloat162float(hx);
    ry = y - __bfloat162float(hy);
    return ((uint32_t)*(uint16_t*)&hy << 16) | *(uint16_t*)&hx;
}
__device__ __forceinline__ void cp16(uint32_t dst, const void* src) {
    asm volatile("cp.async.cg.shared.global [%0], [%1], 16;" :: "r"(dst), "l"(src));
}
__device__ __forceinline__ void cp_commit() {
    asm volatile("cp.async.commit_group;" ::: "memory");
}
template<int N> __device__ __forceinline__ void cp_wait() {
    asm volatile("cp.async.wait_group %0;" :: "n"(N) : "memory");
}

// ---------------- weight pre-split ----------------
__global__ __launch_bounds__(256) void k_wcvt(
    const float* __restrict__ Wq, const float* __restrict__ Wk,
    const float* __restrict__ Wv, const float* __restrict__ Wo)
{
    int m = blockIdx.y;
    const float* src = (m == 0) ? Wq : (m == 1) ? Wk : (m == 2) ? Wv : Wo;
    size_t e = ((size_t)blockIdx.x * 256 + threadIdx.x) * 4;
    float4 v = *(const float4*)(src + e);
    float r0,r1,r2,r3;
    uint2 hi, lo;
    hi.x = pack_hi2(v.x, v.y, r0, r1);
    hi.y = pack_hi2(v.z, v.w, r2, r3);
    lo.x = packbf(r0, r1);
    lo.y = packbf(r2, r3);
    *(uint2*)&w_hi[m][e] = hi;
    *(uint2*)&w_lo[m][e] = lo;
}

// ---------------- LoRA stage 1 (xx inline; 192 thr, 8 rows/CTA) ----------
__global__ __launch_bounds__(192) void k_lora1(
    const float* __restrict__ x, const float* __restrict__ shift,
    const float* __restrict__ maa_x, const float* __restrict__ w1)
{
    __shared__ float xs[8][128];
    int n0 = blockIdx.x * 8;
    int j    = threadIdx.x % 96;
    int half = threadIdx.x / 96;
    float acc[4];
#pragma unroll
    for (int r = 0; r < 4; r++) acc[r] = 0.f;
    for (int k0 = 0; k0 < Cc; k0 += 128) {
        __syncthreads();
        for (int i = threadIdx.x; i < 8*128; i += 192) {
            int r = i >> 7, cc = i & 127;
            int row = n0 + r, c = k0 + cc;
            int t = row & (Tt - 1), b = row >> 10;
            float xv = x[(size_t)row*Cc + c];
            float xp = (t == 0) ? shift[b*Cc + c] : x[(size_t)(row-1)*Cc + c];
            xs[r][cc] = fmaf(xp - xv, maa_x[c], xv);
        }
        __syncthreads();
        for (int k = 0; k < 128; k++) {
            float wv = w1[(k0 + k)*L3 + j];
#pragma unroll
            for (int r = 0; r < 4; r++)
                acc[r] = fmaf(xs[half*4 + r][k], wv, acc[r]);
        }
    }
#pragma unroll
    for (int r = 0; r < 4; r++)
        s_h[(n0 + half*4 + r)*L3 + j] = tanhf(acc[r]);
}

// ---------------- LoRA stage 2 + mixing ----------
__global__ __launch_bounds__(256) void k_mix(
    const float* __restrict__ x, const float* __restrict__ shift,
    const float* __restrict__ w2,
    const float* __restrict__ maa_r, const float* __restrict__ maa_k,
    const float* __restrict__ maa_v)
{
    __shared__ float w2s[96][64];
    __shared__ float hs[16][96];
    int c0 = blockIdx.x * 64;
    int n0 = blockIdx.y * 16;
    int tid = threadIdx.x;
    for (int i = tid; i < 96*64; i += 256) {
        int rr = i >> 6, cc = i & 63;
        w2s[rr][cc] = w2[rr*Cc + c0 + cc];
    }
    for (int i = tid; i < 16*96; i += 256) {
        int rr = i / 96, jj = i % 96;
        hs[rr][jj] = s_h[(n0 + rr)*L3 + jj];
    }
    __syncthreads();
    int col = tid & 63, rg = tid >> 6;
    int c = c0 + col;
    float ar = maa_r[c], ak = maa_k[c], av = maa_v[c];
#pragma unroll
    for (int rr = 0; rr < 4; rr++) {
        int r = rg*4 + rr;
        float m0 = 0.f, m1 = 0.f, m2 = 0.f;
#pragma unroll
        for (int i = 0; i < 32; i++) {
            m0 = fmaf(hs[r][i],      w2s[i][col],      m0);
            m1 = fmaf(hs[r][32 + i], w2s[32 + i][col], m1);
            m2 = fmaf(hs[r][64 + i], w2s[64 + i][col], m2);
        }
        int row = n0 + r;
        int t = row & (Tt - 1), b = row >> 10;
        size_t idx = (size_t)row*Cc + c;
        float xf = x[idx];
        float xp = (t == 0) ? shift[b*Cc + c] : x[idx - Cc];
        float dxf = xp - xf;
        float vr = fmaf(dxf, ar + m0, xf);
        float vk = fmaf(dxf, ak + m1, xf);
        float vv = fmaf(dxf, av + m2, xf);
        __nv_bfloat16 hr = __float2bfloat16_rn(vr);
        __nv_bfloat16 hk = __float2bfloat16_rn(vk);
        __nv_bfloat16 hv = __float2bfloat16_rn(vv);
        a_hi[0][idx] = hr; a_lo[0][idx] = __float2bfloat16_rn(vr - __bfloat162float(hr));
        a_hi[1][idx] = hk; a_lo[1][idx] = __float2bfloat16_rn(vk - __bfloat162float(hk));
        a_hi[2][idx] = hv; a_lo[2][idx] = __float2bfloat16_rn(vv - __bfloat162float(hv));
    }
}

// ===== bf16 3-term GEMM, CTA 128x128, warp tile 64x64, 3-stage cp.async =====
// stage (32KB): A term*8192 + ksub*4096 + row*32 + swz16 ; B 16384 + term*8192
//               + kr*256 + swz_ch*16 (16 n-chunks)
#define GEMM_SMEM_BYTES 98304

__device__ __forceinline__ void gemm_cp(
    const __nv_bfloat16* __restrict__ Ah, const __nv_bfloat16* __restrict__ Al,
    const __nv_bfloat16* __restrict__ Bh, const __nv_bfloat16* __restrict__ Bl,
    float* __restrict__ Cm)
{
    extern __shared__ __align__(16) unsigned char smema[];
    const uint32_t sm0 = cvta_sm(smema);
    const int tid = threadIdx.x, lane = tid & 31, wid = tid >> 5;
    const int wm = wid >> 1, wn = wid & 1;
    const int m0 = blockIdx.y * 128, n0 = blockIdx.x * 128;

    auto issue = [&](int kt, int s) {
        uint32_t SS = sm0 + s*32768;
#pragma unroll
        for (int t = 0; t < 8; t++) {          // A: 2048 x 16B over 128 thr
            int idx = tid + t*128;
            int term = idx >> 9, ksub = (idx >> 8) & 1;
            int row = (idx >> 1) & 127, ch = idx & 1;
            const __nv_bfloat16* src = (term ? Al : Ah)
                + (size_t)(m0 + row)*Cc + kt*32 + ksub*16 + ch*8;
            uint32_t dst = SS + term*8192 + ksub*4096 + row*32
                         + ((ch ^ ((row >> 2) & 1))*16);
            cp16(dst, src);
        }
#pragma unroll
        for (int t = 0; t < 8; t++) {          // B: 2048 x 16B
            int idx = tid + t*128;
            int term = idx >> 9, kr = (idx >> 4) & 31, ch = idx & 15;
            const __nv_bfloat16* src = (term ? Bl : Bh)
                + (size_t)(kt*32 + kr)*Cc + n0 + ch*8;
            uint32_t dst = SS + 16384 + term*8192 + kr*256 + ((ch ^ (kr & 7))*16);
            cp16(dst, src);
        }
        cp_commit();
    };

    float acc[4][8][4];
#pragma unroll
    for (int i = 0; i < 4; i++)
#pragma unroll
        for (int j = 0; j < 8; j++)
#pragma unroll
            for (int e = 0; e < 4; e++) acc[i][j][e] = 0.f;

    const int rlA = lane & 15;
    const int selA = lane >> 4;
    const int krB = ((lane >> 3) & 1)*8 + (lane & 7);
    const int ncB = lane >> 4;

    issue(0, 0);
    issue(1, 1);
    const int NKT = Cc / 32;
    for (int kt = 0; kt < NKT; kt++) {
        if (kt + 1 < NKT) cp_wait<1>(); else cp_wait<0>();
        __syncthreads();
        if (kt + 2 < NKT) issue(kt + 2, (kt + 2) % 3);
        uint32_t SS = sm0 + (kt % 3)*32768;
#pragma unroll
        for (int ksub = 0; ksub < 2; ksub++) {
            uint32_t Ahf[4][4], Alf[4][4], Bhf[8][2], Blf[8][2];
#pragma unroll
            for (int i = 0; i < 4; i++) {
                int row = wm*64 + i*16 + rlA;
                uint32_t off = SS + ksub*4096 + row*32
                             + ((selA ^ ((row >> 2) & 1))*16);
                ldsm_x4(off, Ahf[i]);
                ldsm_x4(off + 8192, Alf[i]);
            }
#pragma unroll
            for (int jj = 0; jj < 4; jj++) {
                int kr = ksub*16 + krB;
                int nchunk = wn*8 + jj*2 + ncB;
                uint32_t off = SS + 16384 + kr*256 + ((nchunk ^ (kr & 7))*16);
                uint32_t tmp[4];
                ldsm_x4t(off, tmp);
                Bhf[2*jj][0] = tmp[0]; Bhf[2*jj][1] = tmp[1];
                Bhf[2*jj+1][0] = tmp[2]; Bhf[2*jj+1][1] = tmp[3];
                ldsm_x4t(off + 8192, tmp);
                Blf[2*jj][0] = tmp[0]; Blf[2*jj][1] = tmp[1];
                Blf[2*jj+1][0] = tmp[2]; Blf[2*jj+1][1] = tmp[3];
            }
#pragma unroll
            for (int i = 0; i < 4; i++)
#pragma unroll
                for (int j = 0; j < 8; j++)
                    mma_bf16(acc[i][j], Ahf[i], Bhf[j]);
#pragma unroll
            for (int i = 0; i < 4; i++)
#pragma unroll
                for (int j = 0; j < 8; j++)
                    mma_bf16(acc[i][j], Ahf[i], Blf[j]);
#pragma unroll
            for (int i = 0; i < 4; i++)
#pragma unroll
                for (int j = 0; j < 8; j++)
                    mma_bf16(acc[i][j], Alf[i], Bhf[j]);
        }
    }

    const int g = lane >> 2, tq = lane & 3;
#pragma unroll
    for (int i = 0; i < 4; i++) {
#pragma unroll
        for (int j = 0; j < 8; j++) {
            int row = m0 + wm*64 + i*16 + g;
            int col = n0 + wn*64 + j*8 + tq*2;
            *(float2*)(Cm + (size_t)row*Cc + col) =
                make_float2(acc[i][j][0], acc[i][j][1]);
            *(float2*)(Cm + (size_t)(row + 8)*Cc + col) =
                make_float2(acc[i][j][2], acc[i][j][3]);
        }
    }
}

__global__ __launch_bounds__(128, 2) void k_gemm_qkv()
{
    int z = blockIdx.z;
    float* C = (z == 0) ? s_yq : (z == 1) ? s_yk : s_yv;
    gemm_cp(a_hi[z], a_lo[z], w_hi[z], w_lo[z], C);
}

__global__ __launch_bounds__(128, 2) void k_gemm_o(float* __restrict__ out)
{
    gemm_cp(o_hi, o_lo, w_hi[3], w_lo[3], out);
}

// ---------------- LN (+RoPE) into head-layout bf16 hi/lo planes -------------
__global__ __launch_bounds__(256) void k_lnqkv(
    const float* __restrict__ gr, const float* __restrict__ br_,
    const float* __restrict__ gk, const float* __restrict__ bk_,
    const float* __restrict__ gv, const float* __restrict__ bv_,
    const float* __restrict__ cosT, const float* __restrict__ sinT)
{
    int mode = blockIdx.y;
    const float* Y; const float* g; const float* bbv;
    __nv_bfloat16 *phi, *plo;
    if (mode == 0)      { Y = s_yq; g = gr; bbv = br_; phi = qp_hi; plo = qp_lo; }
    else if (mode == 1) { Y = s_yk; g = gk; bbv = bk_; phi = kp_hi; plo = kp_lo; }
    else                { Y = s_yv; g = gv; bbv = bv_; phi = vp_hi; plo = vp_lo; }
    int row = blockIdx.x;
    int t = row & (Tt - 1), b = row >> 10;
    __shared__ float srow[Cc];
    __shared__ float red[64];
    const float* yr = Y + (size_t)row*Cc;
    float sum = 0.f, sq = 0.f, vals[8];
#pragma unroll
    for (int k = 0; k < 8; k++) {
        float v = yr[threadIdx.x + k*256];
        vals[k] = v; sum += v; sq = fmaf(v, v, sq);
    }
#pragma unroll
    for (int o = 16; o; o >>= 1) {
        sum += __shfl_xor_sync(0xffffffffu, sum, o);
        sq  += __shfl_xor_sync(0xffffffffu, sq,  o);
    }
    int w = threadIdx.x >> 5;
    if ((threadIdx.x & 31) == 0) { red[w] = sum; red[32 + w] = sq; }
    __syncthreads();
    if (threadIdx.x < 32) {
        float s1 = (threadIdx.x < 8) ? red[threadIdx.x] : 0.f;
        float s2 = (threadIdx.x < 8) ? red[32 + threadIdx.x] : 0.f;
#pragma unroll
        for (int o = 4; o; o >>= 1) {
            s1 += __shfl_xor_sync(0xffffffffu, s1, o);
            s2 += __shfl_xor_sync(0xffffffffu, s2, o);
        }
        if (threadIdx.x == 0) { red[0] = s1; red[32] = s2; }
    }
    __syncthreads();
    float mu  = red[0]  * (1.f/Cc);
    float var = red[32] * (1.f/Cc) - mu*mu;
    float inv = rsqrtf(var + 1e-5f);
#pragma unroll
    for (int k = 0; k < 8; k++) {
        int c = threadIdx.x + k*256;
        srow[c] = (vals[k] - mu)*inv*g[c] + bbv[c];
    }
    __syncthreads();
#pragma unroll
    for (int k = 0; k < 8; k++) {
        int c = threadIdx.x + k*256;
        int h = c >> 6, d = c & 63;
        float o;
        if (mode == 2) { o = srow[c]; }
        else if (d < 32) {
            float cc = cosT[t*32 + d], ss = sinT[t*32 + d];
            o = srow[c]*cc - srow[c + 32]*ss;
        } else {
            int d2 = d - 32;
            float cc = cosT[t*32 + d2], ss = sinT[t*32 + d2];
            o = srow[c - 32]*ss + srow[c]*cc;
        }
        size_t off = (((size_t)(b*Hh + h)*Tt + t) << 6) + d;
        __nv_bfloat16 hv = __float2bfloat16_rn(o);
        phi[off] = hv;
        plo[off] = __float2bfloat16_rn(o - __bfloat162float(hv));
    }
}

// ---------------- LN of attention output (writes bf16 hi/lo) -------------
__global__ __launch_bounds__(256) void k_lnplain(
    const float* __restrict__ gx, const float* __restrict__ bx)
{
    int row = blockIdx.x;
    __shared__ float red[64];
    const float* yr = s_att + (size_t)row*Cc;
    float sum = 0.f, sq = 0.f, vals[8];
#pragma unroll
    for (int k = 0; k < 8; k++) {
        float v = yr[threadIdx.x + k*256];
        vals[k] = v; sum += v; sq = fmaf(v, v, sq);
    }
#pragma unroll
    for (int o = 16; o; o >>= 1) {
        sum += __shfl_xor_sync(0xffffffffu, sum, o);
        sq  += __shfl_xor_sync(0xffffffffu, sq,  o);
    }
    int w = threadIdx.x >> 5;
    if ((threadIdx.x & 31) == 0) { red[w] = sum; red[32 + w] = sq; }
    __syncthreads();
    if (threadIdx.x < 32) {
        float s1 = (threadIdx.x < 8) ? red[threadIdx.x] : 0.f;
        float s2 = (threadIdx.x < 8) ? red[32 + threadIdx.x] : 0.f;
#pragma unroll
        for (int o = 4; o; o >>= 1) {
            s1 += __shfl_xor_sync(0xffffffffu, s1, o);
            s2 += __shfl_xor_sync(0xffffffffu, s2, o);
        }
        if (threadIdx.x == 0) { red[0] = s1; red[32] = s2; }
    }
    __syncthreads();
    float mu  = red[0]  * (1.f/Cc);
    float var = red[32] * (1.f/Cc) - mu*mu;
    float inv = rsqrtf(var + 1e-5f);
    size_t rb = (size_t)row*Cc;
#pragma unroll
    for (int k = 0; k < 8; k++) {
        int c = threadIdx.x + k*256;
        float v = (vals[k] - mu)*inv*gx[c] + bx[c];
        __nv_bfloat16 hv = __float2bfloat16_rn(v);
        o_hi[rb + c] = hv;
        o_lo[rb + c] = __float2bfloat16_rn(v - __bfloat162float(hv));
    }
}

// ======== causal flash attention: cp.async pre-split tiles, 3x-bf16 ========
#define ATTN_SMEM_BYTES 81920

__global__ __launch_bounds__(128, 2) void k_attn_tc()
{
    extern __shared__ __align__(16) unsigned char asmem[];
    const uint32_t sb = cvta_sm(asmem);

    const int qt  = (int)gridDim.x - 1 - (int)blockIdx.x;
    const int bh  = blockIdx.y;
    const int b   = bh >> 5, h = bh & 31;
    const int tid = threadIdx.x, lane = tid & 31, w = tid >> 5;
    const int q0  = qt * 64;
    const size_t basebh = (size_t)bh*Tt*64;

    auto issueKV = [&](int kt2, int s) {
        uint32_t SS = sb + 16384 + s*32768;
        int s0 = kt2*64;
#pragma unroll
        for (int i = 0; i < 4; i++) {
            int idx = tid + i*128;
            int row = idx >> 3, ch = idx & 7;
            uint32_t o = (uint32_t)((row*8 + (ch ^ (row & 7)))*16);
            size_t src = basebh + (size_t)(s0 + row)*64 + ch*8;
            cp16(SS + o,         kp_hi + src);
            cp16(SS + 8192 + o,  kp_lo + src);
            cp16(SS + 16384 + o, vp_hi + src);
            cp16(SS + 24576 + o, vp_lo + src);
        }
        cp_commit();
    };

    {
#pragma unroll
        for (int i = 0; i < 4; i++) {
            int idx = tid + i*128;
            int row = idx >> 3, ch = idx & 7;
            uint32_t o = (uint32_t)((row*8 + (ch ^ (row & 7)))*16);
            size_t src = basebh + (size_t)(q0 + row)*64 + ch*8;
            cp16(sb + o,        qp_hi + src);
            cp16(sb + 8192 + o, qp_lo + src);
        }
        cp_commit();
    }
    issueKV(0, 0);
    cp_wait<1>();
    __syncthreads();

    uint32_t qh[4][4], ql[4][4];
    const int g8 = lane >> 3, rr8 = lane & 7;
#pragma unroll
    for (int kk = 0; kk < 4; kk++) {
        int row = w*16 + (g8 & 1)*8 + rr8;
        int ch  = kk*2 + (g8 >> 1);
        uint32_t off = (uint32_t)(row*8 + (ch ^ (row & 7)))*16;
        ldsm_x4(sb + off, qh[kk]);
        ldsm_x4(sb + 8192 + off, ql[kk]);
    }

    float o[8][4];
#pragma unroll
    for (int j = 0; j < 8; j++)
#pragma unroll
        for (int e = 0; e < 4; e++) o[j][e] = 0.f;
    float m0 = -1e30f, m1 = -1e30f, l0 = 0.f, l1 = 0.f;

    for (int kt = 0; kt <= qt; kt++) {
        if (kt + 1 <= qt) { issueKV(kt + 1, (kt + 1) & 1); cp_wait<1>(); }
        else              { cp_wait<0>(); }
        __syncthreads();
        const uint32_t SK = sb + 16384 + (kt & 1)*32768;
        const uint32_t SV = SK + 16384;

        float c[8][4];
#pragma unroll
        for (int j = 0; j < 8; j++)
#pragma unroll
            for (int e = 0; e < 4; e++) c[j][e] = 0.f;
#pragma unroll
        for (int kk = 0; kk < 4; kk++) {
            uint32_t kbh[4][4], kbl[4][4];
#pragma unroll
            for (int u = 0; u < 4; u++) {
                int row = u*16 + (g8 >> 1)*8 + rr8;
                int ch  = kk*2 + (g8 & 1);
                uint32_t off = (uint32_t)(row*8 + (ch ^ (row & 7)))*16;
                ldsm_x4(SK + off, kbh[u]);
                ldsm_x4(SK + 8192 + off, kbl[u]);
            }
#pragma unroll
            for (int u = 0; u < 4; u++) {
                mma_bf16(c[2*u],   qh[kk], &kbh[u][0]);
                mma_bf16(c[2*u+1], qh[kk], &kbh[u][2]);
            }
#pragma unroll
            for (int u = 0; u < 4; u++) {
                mma_bf16(c[2*u],   qh[kk], &kbl[u][0]);
                mma_bf16(c[2*u+1], qh[kk], &kbl[u][2]);
            }
#pragma unroll
            for (int u = 0; u < 4; u++) {
                mma_bf16(c[2*u],   ql[kk], &kbh[u][0]);
                mma_bf16(c[2*u+1], ql[kk], &kbh[u][2]);
            }
        }
        const int rl0 = w*16 + (lane >> 2);
#pragma unroll
        for (int j = 0; j < 8; j++)
#pragma unroll
            for (int e = 0; e < 4; e++) c[j][e] *= 0.125f;
        if (kt == qt) {
#pragma unroll
            for (int j = 0; j < 8; j++) {
                int col = j*8 + 2*(lane & 3);
                if (col     > rl0)     c[j][0] = -1e30f;
                if (col + 1 > rl0)     c[j][1] = -1e30f;
                if (col     > rl0 + 8) c[j][2] = -1e30f;
                if (col + 1 > rl0 + 8) c[j][3] = -1e30f;
            }
        }
        float mx0 = -1e30f, mx1 = -1e30f;
#pragma unroll
        for (int j = 0; j < 8; j++) {
            mx0 = fmaxf(mx0, fmaxf(c[j][0], c[j][1]));
            mx1 = fmaxf(mx1, fmaxf(c[j][2], c[j][3]));
        }
        mx0 = fmaxf(mx0, __shfl_xor_sync(0xffffffffu, mx0, 1));
        mx0 = fmaxf(mx0, __shfl_xor_sync(0xffffffffu, mx0, 2));
        mx1 = fmaxf(mx1, __shfl_xor_sync(0xffffffffu, mx1, 1));
        mx1 = fmaxf(mx1, __shfl_xor_sync(0xffffffffu, mx1, 2));
        float mn0 = fmaxf(m0, mx0), mn1 = fmaxf(m1, mx1);
        float a0 = __expf(m0 - mn0), a1 = __expf(m1 - mn1);
        m0 = mn0; m1 = mn1;

        uint32_t ph[4][4], pl[4][4];
        float rs0 = 0.f, rs1 = 0.f;
#pragma unroll
        for (int t = 0; t < 4; t++) {
            float p00 = __expf(c[2*t][0]   - mn0), p01 = __expf(c[2*t][1]   - mn0);
            float p02 = __expf(c[2*t][2]   - mn1), p03 = __expf(c[2*t][3]   - mn1);
            float p10 = __expf(c[2*t+1][0] - mn0), p11 = __expf(c[2*t+1][1] - mn0);
            float p12 = __expf(c[2*t+1][2] - mn1), p13 = __expf(c[2*t+1][3] - mn1);
            rs0 += p00 + p01 + p10 + p11;
            rs1 += p02 + p03 + p12 + p13;
            float e0, e1;
            ph[t][0] = pack_hi2(p00, p01, e0, e1); pl[t][0] = packbf(e0, e1);
            ph[t][1] = pack_hi2(p02, p03, e0, e1); pl[t][1] = packbf(e0, e1);
            ph[t][2] = pack_hi2(p10, p11, e0, e1); pl[t][2] = packbf(e0, e1);
            ph[t][3] = pack_hi2(p12, p13, e0, e1); pl[t][3] = packbf(e0, e1);
        }
        rs0 += __shfl_xor_sync(0xffffffffu, rs0, 1);
        rs0 += __shfl_xor_sync(0xffffffffu, rs0, 2);
        rs1 += __shfl_xor_sync(0xffffffffu, rs1, 1);
        rs1 += __shfl_xor_sync(0xffffffffu, rs1, 2);
        l0 = l0*a0 + rs0;
        l1 = l1*a1 + rs1;
#pragma unroll
        for (int j = 0; j < 8; j++) {
            o[j][0] *= a0; o[j][1] *= a0;
            o[j][2] *= a1; o[j][3] *= a1;
        }
#pragma unroll
        for (int t = 0; t < 4; t++) {
#pragma unroll
            for (int u = 0; u < 4; u++) {
                int row = t*16 + (g8 & 1)*8 + rr8;
                int ch  = u*2 + (g8 >> 1);
                uint32_t off = (uint32_t)(row*8 + (ch ^ (row & 7)))*16;
                uint32_t vh_[4], vl_[4];
                ldsm_x4t(SV + off, vh_);
                ldsm_x4t(SV + 8192 + off, vl_);
                mma_bf16(o[2*u],   ph[t], &vh_[0]);
                mma_bf16(o[2*u+1], ph[t], &vh_[2]);
                mma_bf16(o[2*u],   pl[t], &vh_[0]);
                mma_bf16(o[2*u+1], pl[t], &vh_[2]);
                mma_bf16(o[2*u],   ph[t], &vl_[0]);
                mma_bf16(o[2*u+1], ph[t], &vl_[2]);
            }
        }
        __syncthreads();
    }

    float inv0 = 1.f / l0, inv1 = 1.f / l1;
    int rg0 = q0 + w*16 + (lane >> 2);
    float* base0 = s_att + (size_t)(b*Tt + rg0)*Cc + h*64;
    float* base1 = base0 + (size_t)8*Cc;
#pragma unroll
    for (int j = 0; j < 8; j++) {
        int colo = j*8 + 2*(lane & 3);
        *(float2*)(base0 + colo) = make_float2(o[j][0]*inv0, o[j][1]*inv0);
        *(float2*)(base1 + colo) = make_float2(o[j][2]*inv1, o[j][3]*inv1);
    }
}

// ---------------- launch ----------------
extern "C" void kernel_launch(void* const* d_in, const int* in_sizes, int n_in,
                              void* d_out, int out_size)
{
    (void)in_sizes; (void)n_in; (void)out_size;
    const float* x     = (const float*)d_in[0];
    const float* shift = (const float*)d_in[1];
    const float* maa_x = (const float*)d_in[2];
    const float* maa_r = (const float*)d_in[3];
    const float* maa_k = (const float*)d_in[4];
    const float* maa_v = (const float*)d_in[5];
    const float* w1    = (const float*)d_in[6];
    const float* w2    = (const float*)d_in[7];
    const float* Wq    = (const float*)d_in[8];
    const float* Wk    = (const float*)d_in[9];
    const float* Wv    = (const float*)d_in[10];
    const float* Wo    = (const float*)d_in[11];
    const float* g_r   = (const float*)d_in[12];
    const float* b_r   = (const float*)d_in[13];
    const float* g_k   = (const float*)d_in[14];
    const float* b_k   = (const float*)d_in[15];
    const float* g_v   = (const float*)d_in[16];
    const float* b_v   = (const float*)d_in[17];
    const float* g_x   = (const float*)d_in[18];
    const float* b_x   = (const float*)d_in[19];
    const float* cosT  = (const float*)d_in[20];
    const float* sinT  = (const float*)d_in[21];
    float* out = (float*)d_out;

    cudaFuncSetAttribute(k_gemm_qkv, cudaFuncAttributeMaxDynamicSharedMemorySize,
                         GEMM_SMEM_BYTES);
    cudaFuncSetAttribute(k_gemm_o, cudaFuncAttributeMaxDynamicSharedMemorySize,
                         GEMM_SMEM_BYTES);
    cudaFuncSetAttribute(k_attn_tc, cudaFuncAttributeMaxDynamicSharedMemorySize,
                         ATTN_SMEM_BYTES);

    k_wcvt<<<dim3(Cc*Cc/1024, 4), 256>>>(Wq, Wk, Wv, Wo);
    k_lora1<<<NT/8, 192>>>(x, shift, maa_x, w1);
    k_mix<<<dim3(Cc/64, NT/16), 256>>>(x, shift, w2, maa_r, maa_k, maa_v);
    k_gemm_qkv<<<dim3(16, 16, 3), 128, GEMM_SMEM_BYTES>>>();
    k_lnqkv<<<dim3(NT, 3), 256>>>(g_r, b_r, g_k, b_k, g_v, b_v, cosT, sinT);
    k_attn_tc<<<dim3(16, Bb*Hh), 128, ATTN_SMEM_BYTES>>>();
    k_lnplain<<<NT, 256>>>(g_x, b_x);
    k_gemm_o<<<dim3(16, 16), 128, GEMM_SMEM_BYTES>>>(out);
}